// round 2
// baseline (speedup 1.0000x reference)
#include <cuda_runtime.h>
#include <math.h>
#include <float.h>

#define D_TOT   496
#define F_TOT   40
#define T_STEPS 1000
#define B_MAX   32768
#define GROUPS  8
#define GCOLS   62
#define RTILE   256

// ---------------- device scratch (no runtime allocations allowed) ----------------
__device__ float g_log_alpha[T_STEPS];
__device__ float g_log_1m_alpha[T_STEPS];
__device__ float g_log_ca[T_STEPS];
__device__ float g_log_1m_ca[T_STEPS];
__device__ float g_cspart[16 * D_TOT];
__device__ float g_colsum[D_TOT];
__device__ int   g_win[B_MAX * F_TOT];
__device__ float g_part[B_MAX * GROUPS];
__device__ float g_red1[64];

// ---------------- helpers ----------------
__device__ __forceinline__ float lae_prec(float a, float b) {   // precise logaddexp
    float m = fmaxf(a, b), n = fminf(a, b);
    return m + log1pf(expf(n - m));
}
__device__ __forceinline__ float lae_fast(float a, float b) {   // fast logaddexp
    float m = fmaxf(a, b), n = fminf(a, b);
    return m + __logf(1.0f + __expf(n - m));
}

// Lane layout: each lane owns 2 adjacent columns (one float2) of ONE feature.
// Features per group have sizes 2,4,8,16,32 at group-local cols
// [0,2),[2,6),[6,14),[14,30),[30,62). Lanes are permuted so each feature's
// lane-range is power-of-2 sized AND aligned:
//   la4 (32cls,16 lanes): lanes [0,16)  -> colpairs 15..30
//   la3 (16cls, 8 lanes): lanes [16,24) -> colpairs  7..14
//   la2 ( 8cls, 4 lanes): lanes [24,28) -> colpairs  3..6
//   la1 ( 4cls, 2 lanes): lanes [28,30) -> colpairs  1..2
//   la0 ( 2cls, 1 lane ): lane 30       -> colpair   0
//   lane 31: pad
struct Lane { int la, widthL, lbase, cp, sstart; float lnc; };
__device__ __forceinline__ Lane laneLayout(int lane) {
    Lane L;
    if (lane < 16)      { L.la=4; L.widthL=16; L.lbase=0;  L.cp=15+lane; L.sstart=30; L.lnc=3.46573590f; }
    else if (lane < 24) { L.la=3; L.widthL=8;  L.lbase=16; L.cp=lane-9;  L.sstart=14; L.lnc=2.77258872f; }
    else if (lane < 28) { L.la=2; L.widthL=4;  L.lbase=24; L.cp=lane-21; L.sstart=6;  L.lnc=2.07944154f; }
    else if (lane < 30) { L.la=1; L.widthL=2;  L.lbase=28; L.cp=lane-27; L.sstart=2;  L.lnc=1.38629436f; }
    else if (lane == 30){ L.la=0; L.widthL=1;  L.lbase=30; L.cp=0;       L.sstart=0;  L.lnc=0.69314718f; }
    else                { L.la=0; L.widthL=0;  L.lbase=31; L.cp=0;       L.sstart=0;  L.lnc=0.69314718f; }
    return L;
}

__device__ __forceinline__ float segMax(float v, int widthL) {
#pragma unroll
    for (int d = 1; d < 16; d <<= 1) {
        float o = __shfl_xor_sync(0xFFFFFFFFu, v, d);
        if (widthL > d) v = fmaxf(v, o);
    }
    return v;
}
__device__ __forceinline__ float segSum(float v, int widthL) {
#pragma unroll
    for (int d = 1; d < 16; d <<= 1) {
        float o = __shfl_xor_sync(0xFFFFFFFFu, v, d);
        if (widthL > d) v += o;
    }
    return v;
}

// ---------------- prologue: diffusion tables + W column sums ----------------
__global__ void k_prep(const float* __restrict__ W) {
    int tid = threadIdx.x;
    if (blockIdx.x == 0) {
        __shared__ double sd[1024];
        double lad = 0.0;
        if (tid < T_STEPS) {
            double beta = 1e-4 + (double)tid * ((0.02 - 1e-4) / 999.0);
            double alpha = 1.0 - beta;
            lad = log(alpha);
            g_log_alpha[tid] = (float)lad;
            g_log_1m_alpha[tid] = (float)log(beta);
        }
        sd[tid] = lad;
        __syncthreads();
        for (int off = 1; off < 1024; off <<= 1) {
            double add = (tid >= off) ? sd[tid - off] : 0.0;
            __syncthreads();
            sd[tid] += add;
            __syncthreads();
        }
        if (tid < T_STEPS) {
            double cum = sd[tid];
            g_log_ca[tid] = (float)cum;
            g_log_1m_ca[tid] = (float)log(-expm1(cum));
        }
    } else {
        int p = blockIdx.x - 1;
        int r0 = p * 31;
        if (tid < D_TOT) {
            float acc = 0.f;
#pragma unroll
            for (int r = 0; r < 31; r++)
                acc += W[(r0 + r) * D_TOT + tid];
            g_cspart[p * D_TOT + tid] = acc;
        }
    }
}
__global__ void k_csfin() {
    int j = threadIdx.x;
    if (j < D_TOT) {
        float s = 0.f;
#pragma unroll
        for (int p = 0; p < 16; p++) s += g_cspart[p * D_TOT + j];
        g_colsum[j] = s;
    }
}

// ---------------- K1: Gumbel-max sampling (bit-faithful precise path) ----------------
__global__ void __launch_bounds__(256) k_sample(
    const int* __restrict__ x0, const int* __restrict__ ts,
    const float* __restrict__ uni)
{
    const int row = blockIdx.x, tid = threadIdx.x;
    const int lane = tid & 31, g = tid >> 5;
    Lane L = laneLayout(lane);
    const bool valid = (L.widthL > 0);
    const int t = __ldg(&ts[row]);
    const float lc = g_log_ca[t], l1c = g_log_1m_ca[t];
    const int feat = g * 5 + L.la;
    const int x0v = valid ? __ldg(&x0[row * F_TOT + feat]) : 0;
    const float LOGEPS = -69.07755279f;
    const int c0 = 2 * L.cp;                   // group-local col of slot 0
    const int hot = L.sstart + x0v;
    const float qb = l1c - L.lnc;              // exact cold value of logaddexp
    const float qhot = lae_prec(lc, qb);       // exact hot value
    const float qp0 = (c0 == hot)     ? qhot : qb;
    const float qp1 = (c0 + 1 == hot) ? qhot : qb;

    float2 u = make_float2(0.5f, 0.5f);
    if (valid) u = *(const float2*)(uni + (size_t)row * D_TOT + g * GCOLS + c0);
    const float gm0 = -logf(-logf(u.x + 1e-30f) + 1e-30f);
    const float gm1 = -logf(-logf(u.y + 1e-30f) + 1e-30f);

    float z0 = qp0 + gm0, z1 = qp1 + gm1;
    float zv; int zi;
    if (!valid)        { zv = -FLT_MAX; zi = 0x7FFFFFFF; }
    else if (z0 >= z1) { zv = z0; zi = g * GCOLS + c0; }       // first-max tie break
    else               { zv = z1; zi = g * GCOLS + c0 + 1; }
#pragma unroll
    for (int d = 1; d < 16; d <<= 1) {
        float ov = __shfl_xor_sync(0xFFFFFFFFu, zv, d);
        int   oi = __shfl_xor_sync(0xFFFFFFFFu, zi, d);
        if (L.widthL > d && (ov > zv || (ov == zv && oi < zi))) { zv = ov; zi = oi; }
    }
    if (valid && lane == L.lbase) g_win[row * F_TOT + feat] = zi;
}

// ---------------- K2: fused gather + posteriors + KL (SMEM-staged W) ----------------
#define SMEM_K2 (D_TOT*31*8 + RTILE*F_TOT*4*2 + RTILE*4)

__global__ void __launch_bounds__(256) k_fuse(
    const int* __restrict__ x0, const int* __restrict__ ts,
    const float* __restrict__ W, const float* __restrict__ bias,
    const float* __restrict__ temb, int B)
{
    extern __shared__ char smem[];
    float2* sW2  = (float2*)smem;                           // [496][31] float2
    int* sWinT   = (int*)(smem + D_TOT * 31 * 8);           // [RTILE][40]
    int* sX0T    = sWinT + RTILE * F_TOT;                   // [RTILE][40]
    int* sTT     = sX0T + RTILE * F_TOT;                    // [RTILE]

    const int tile = blockIdx.x, g = blockIdx.y;
    const int tid = threadIdx.x, lane = tid & 31, wid = tid >> 5;
    const int gbase = g * GCOLS;
    const int row0 = tile * RTILE;

    // stage W[:, group] (31 float2 per row, coalesced)
    {
        const int cc = tid & 31;
        for (int r = tid >> 5; r < D_TOT; r += 8)
            if (cc < 31)
                sW2[r * 31 + cc] = *(const float2*)(W + (size_t)r * D_TOT + gbase + 2 * cc);
    }
    // stage winners + x0 + t for the row tile
    for (int i = tid; i < RTILE * F_TOT; i += 256) {
        int r = row0 + i / F_TOT;
        bool ok = (r < B);
        int gi = row0 * F_TOT + i;
        sWinT[i] = ok ? g_win[gi] : 0;
        sX0T[i]  = ok ? x0[gi]    : 0;
    }
    if (tid < RTILE) sTT[tid] = (row0 + tid < B) ? ts[row0 + tid] : 0;
    __syncthreads();

    Lane L = laneLayout(lane);
    const bool valid = (L.widthL > 0);
    const int C0 = gbase + 2 * L.cp;                 // global col of slot 0
    const int feat = g * 5 + L.la;
    const float LOGEPS = -69.07755279f;
    const float lcT  = g_log_ca[T_STEPS - 1];
    const float l1cT = g_log_1m_ca[T_STEPS - 1];
    const float2 cs2 = *(const float2*)(g_colsum + C0);
    const float2 b2  = *(const float2*)(bias + C0);
    const float NEG = -FLT_MAX;
    const float qbT = l1cT - L.lnc;

    for (int rl = wid; rl < RTILE; rl += 8) {
        const int row = row0 + rl;
        if (row >= B) break;
        const int t = sTT[rl];
        const int tm1 = (t > 0) ? (t - 1) : 0;
        const float laa  = __ldg(&g_log_alpha[t]);
        const float l1a  = __ldg(&g_log_1m_alpha[t]);
        const float lcm  = __ldg(&g_log_ca[tm1]);
        const float l1cm = __ldg(&g_log_1m_ca[tm1]);
        const bool t0 = (t == 0);

        const int x0v = sX0T[rl * F_TOT + feat];
        const int hot = L.sstart + x0v;              // group-local
        const int c0l = 2 * L.cp;
        const bool h0 = (c0l == hot), h1 = (c0l + 1 == hot);
        const int wcol = sWinT[rl * F_TOT + feat];   // global winner col
        const bool w0 = (C0 == wcol), w1 = (C0 + 1 == wcol);

        // ---- gather: sum of 40 winner rows of the W group-block (SMEM) ----
        int wlo = sWinT[rl * F_TOT + lane];
        int whi = sWinT[rl * F_TOT + 32 + (lane & 7)];
        float g0 = 0.f, g1 = 0.f;
#pragma unroll
        for (int f = 0; f < 40; f++) {
            int wr = (f < 32) ? __shfl_sync(0xFFFFFFFFu, wlo, f)
                              : __shfl_sync(0xFFFFFFFFu, whi, f - 32);
            float2 v = sW2[wr * 31 + L.cp];
            g0 += v.x; g1 += v.y;
        }
        const float2 te = *(const float2*)(temb + (size_t)t * D_TOT + C0);
        const float p0 = LOGEPS * (cs2.x - g0) + b2.x + te.x;
        const float p1 = LOGEPS * (cs2.y - g1) + b2.y + te.y;

        // per-segment log-softmax of pred
        float m = valid ? fmaxf(p0, p1) : NEG;
        m = segMax(m, L.widthL);
        float s = valid ? (__expf(p0 - m) + __expf(p1 - m)) : 0.f;
        s = segSum(s, L.widthL);
        const float lse = m + __logf(s);
        const float lh00 = p0 - lse, lh01 = p1 - lse;

        const float qb1 = l1a - L.lnc;
        const float qbm = l1cm - L.lnc;
        const float lxt0 = w0 ? 0.f : LOGEPS, lxt1 = w1 ? 0.f : LOGEPS;
        const float lx00 = h0 ? 0.f : LOGEPS, lx01 = h1 ? 0.f : LOGEPS;

        const float qo0 = lae_fast(lxt0 + laa, qb1);
        const float qo1 = lae_fast(lxt1 + laa, qb1);
        const float ev0 = t0 ? lx00 : lae_fast(lx00 + lcm, qbm);
        const float ev1 = t0 ? lx01 : lae_fast(lx01 + lcm, qbm);
        const float un0 = ev0 + qo0, un1 = ev1 + qo1;
        const float e20 = t0 ? lh00 : lae_fast(lh00 + lcm, qbm);
        const float e21 = t0 ? lh01 : lae_fast(lh01 + lcm, qbm);
        const float v20 = e20 + qo0, v21 = e21 + qo1;

        float m1 = valid ? fmaxf(un0, un1) : NEG; m1 = segMax(m1, L.widthL);
        float s1 = valid ? (__expf(un0 - m1) + __expf(un1 - m1)) : 0.f; s1 = segSum(s1, L.widthL);
        const float n1 = m1 + __logf(s1);
        float m2 = valid ? fmaxf(v20, v21) : NEG; m2 = segMax(m2, L.widthL);
        float s2 = valid ? (__expf(v20 - m2) + __expf(v21 - m2)) : 0.f; s2 = segSum(s2, L.widthL);
        const float n2 = m2 + __logf(s2);

        const float lt0 = un0 - n1, lt1 = un1 - n1;
        const float le0 = v20 - n2, le1 = v21 - n2;
        const float kl = __expf(lt0) * (lt0 - le0) + __expf(lt1) * (lt1 - le1);
        const float de = -((h0 ? le0 : 0.f) + (h1 ? le1 : 0.f));
        const float lq0 = lae_fast(lx00 + lcT, qbT);
        const float lq1 = lae_fast(lx01 + lcT, qbT);
        const float pr = __expf(lq0) * (lq0 + L.lnc) + __expf(lq1) * (lq1 + L.lnc);

        float contrib = valid ? ((t0 ? de : kl) * 1000.f + pr) : 0.f;
#pragma unroll
        for (int d = 1; d < 32; d <<= 1)
            contrib += __shfl_xor_sync(0xFFFFFFFFu, contrib, d);
        if (lane == 0) g_part[row * GROUPS + g] = contrib;
    }
}

// ---------------- deterministic two-stage mean ----------------
__global__ void k_red1(int n) {
    __shared__ float s[1024];
    const int per = (n + 63) >> 6;
    const int b = blockIdx.x;
    int end = (b + 1) * per; if (end > n) end = n;
    float a = 0.f;
    for (int i = b * per + threadIdx.x; i < end; i += 1024) a += g_part[i];
    s[threadIdx.x] = a;
    __syncthreads();
    for (int off = 512; off > 0; off >>= 1) {
        if (threadIdx.x < off) s[threadIdx.x] += s[threadIdx.x + off];
        __syncthreads();
    }
    if (threadIdx.x == 0) g_red1[b] = s[0];
}
__global__ void k_red2(float* __restrict__ out, int B) {
    if (threadIdx.x == 0) {
        float s = 0.f;
#pragma unroll
        for (int i = 0; i < 64; i++) s += g_red1[i];
        out[0] = s / (float)B;
    }
}

// ---------------- launch ----------------
extern "C" void kernel_launch(void* const* d_in, const int* in_sizes, int n_in,
                              void* d_out, int out_size) {
    const int*   x0   = (const int*)d_in[0];
    const int*   ts   = (const int*)d_in[1];
    const float* uni  = (const float*)d_in[2];
    const float* W    = (const float*)d_in[3];
    const float* bias = (const float*)d_in[4];
    const float* temb = (const float*)d_in[5];
    float* out = (float*)d_out;
    const int B = in_sizes[1];

    cudaFuncSetAttribute(k_fuse, cudaFuncAttributeMaxDynamicSharedMemorySize, SMEM_K2);

    k_prep<<<17, 1024>>>(W);
    k_csfin<<<1, 512>>>();
    k_sample<<<B, 256>>>(x0, ts, uni);
    dim3 gridF((B + RTILE - 1) / RTILE, GROUPS);
    k_fuse<<<gridF, 256, SMEM_K2>>>(x0, ts, W, bias, temb, B);
    k_red1<<<64, 1024>>>(B * GROUPS);
    k_red2<<<1, 32>>>(out, B);
}

// round 3
// speedup vs baseline: 1.6915x; 1.6915x over previous
#include <cuda_runtime.h>
#include <math.h>
#include <float.h>

#define D_TOT   496
#define F_TOT   40
#define T_STEPS 1000
#define B_MAX   32768
#define GROUPS  8
#define GCOLS   62
#define NTILES  18
#define FULLM   0xFFFFFFFFu

// ---------------- device scratch (no runtime allocations allowed) ----------------
__device__ float g_log_alpha[T_STEPS];
__device__ float g_log_1m_alpha[T_STEPS];
__device__ float g_log_ca[T_STEPS];
__device__ float g_log_1m_ca[T_STEPS];
__device__ float g_cspart[16 * D_TOT];
__device__ float g_colsum[D_TOT];
__device__ int   g_win[B_MAX * F_TOT];
__device__ float g_part[B_MAX * GROUPS];
__device__ float g_red1[64];

// ---------------- helpers ----------------
__device__ __forceinline__ float lae_prec(float a, float b) {
    float m = fmaxf(a, b), n = fminf(a, b);
    return m + log1pf(expf(n - m));
}
__device__ __forceinline__ float lae_fast(float a, float b) {
    float m = fmaxf(a, b), n = fminf(a, b);
    return m + __logf(1.0f + __expf(n - m));
}

// Lane layout: each lane owns 2 adjacent columns (one float2) of ONE feature.
// Feature sizes 2,4,8,16,32 at group-local cols [0,2),[2,6),[6,14),[14,30),[30,62).
//   la4 (32cls,16 lanes): lanes [0,16)  -> colpairs 15..30
//   la3 (16cls, 8 lanes): lanes [16,24) -> colpairs  7..14
//   la2 ( 8cls, 4 lanes): lanes [24,28) -> colpairs  3..6
//   la1 ( 4cls, 2 lanes): lanes [28,30) -> colpairs  1..2
//   la0 ( 2cls, 1 lane ): lane 30       -> colpair   0
//   lane 31: pad
struct Lane { int la, widthL, lbase, cp, sstart; float lnc; };
__device__ __forceinline__ Lane laneLayout(int lane) {
    Lane L;
    if (lane < 16)      { L.la=4; L.widthL=16; L.lbase=0;  L.cp=15+lane; L.sstart=30; L.lnc=3.46573590f; }
    else if (lane < 24) { L.la=3; L.widthL=8;  L.lbase=16; L.cp=lane-9;  L.sstart=14; L.lnc=2.77258872f; }
    else if (lane < 28) { L.la=2; L.widthL=4;  L.lbase=24; L.cp=lane-21; L.sstart=6;  L.lnc=2.07944154f; }
    else if (lane < 30) { L.la=1; L.widthL=2;  L.lbase=28; L.cp=lane-27; L.sstart=2;  L.lnc=1.38629436f; }
    else if (lane == 30){ L.la=0; L.widthL=1;  L.lbase=30; L.cp=0;       L.sstart=0;  L.lnc=0.69314718f; }
    else                { L.la=0; L.widthL=0;  L.lbase=31; L.cp=0;       L.sstart=0;  L.lnc=0.69314718f; }
    return L;
}
// group-local colpair -> owning lane
__device__ __forceinline__ int cpToLane(int cp) {
    return (cp >= 15) ? cp - 15 : (cp >= 7) ? cp + 9 : (cp >= 3) ? cp + 21
         : (cp >= 1) ? cp + 27 : 30;
}

__device__ __forceinline__ float segMax(float v, int widthL) {
#pragma unroll
    for (int d = 1; d < 16; d <<= 1) {
        float o = __shfl_xor_sync(FULLM, v, d);
        if (widthL > d) v = fmaxf(v, o);
    }
    return v;
}
__device__ __forceinline__ float segSum(float v, int widthL) {
#pragma unroll
    for (int d = 1; d < 16; d <<= 1) {
        float o = __shfl_xor_sync(FULLM, v, d);
        if (widthL > d) v += o;
    }
    return v;
}

// ---------------- prologue: diffusion tables + W column sums ----------------
__global__ void k_prep(const float* __restrict__ W) {
    int tid = threadIdx.x;
    if (blockIdx.x == 0) {
        __shared__ double sd[1024];
        double lad = 0.0;
        if (tid < T_STEPS) {
            double beta = 1e-4 + (double)tid * ((0.02 - 1e-4) / 999.0);
            double alpha = 1.0 - beta;
            lad = log(alpha);
            g_log_alpha[tid] = (float)lad;
            g_log_1m_alpha[tid] = (float)log(beta);
        }
        sd[tid] = lad;
        __syncthreads();
        for (int off = 1; off < 1024; off <<= 1) {
            double add = (tid >= off) ? sd[tid - off] : 0.0;
            __syncthreads();
            sd[tid] += add;
            __syncthreads();
        }
        if (tid < T_STEPS) {
            double cum = sd[tid];
            g_log_ca[tid] = (float)cum;
            g_log_1m_ca[tid] = (float)log(-expm1(cum));
        }
    } else {
        int p = blockIdx.x - 1;
        int r0 = p * 31;
        if (tid < D_TOT) {
            float acc = 0.f;
#pragma unroll
            for (int r = 0; r < 31; r++)
                acc += W[(r0 + r) * D_TOT + tid];
            g_cspart[p * D_TOT + tid] = acc;
        }
    }
}
__global__ void k_csfin() {
    int j = threadIdx.x;
    if (j < D_TOT) {
        float s = 0.f;
#pragma unroll
        for (int p = 0; p < 16; p++) s += g_cspart[p * D_TOT + j];
        g_colsum[j] = s;
    }
}

// ---------------- K1: Gumbel-max sampling (u-monotone fast path) ----------------
__global__ void __launch_bounds__(256) k_sample(
    const int* __restrict__ x0, const int* __restrict__ ts,
    const float* __restrict__ uni)
{
    const int row = blockIdx.x, tid = threadIdx.x;
    const int lane = tid & 31, g = tid >> 5;
    Lane L = laneLayout(lane);
    const bool valid = (L.widthL > 0);
    const int t = __ldg(&ts[row]);
    const float lc = g_log_ca[t], l1c = g_log_1m_ca[t];
    const int feat = g * 5 + L.la;
    const int x0v = valid ? __ldg(&x0[row * F_TOT + feat]) : 0;
    const int hot = L.sstart + x0v;                // group-local hot col
    const float qb = l1c - L.lnc;                  // cold q_prior value (exact)
    const int c0 = 2 * L.cp;

    float2 u = make_float2(0.f, 0.f);
    if (valid) u = *(const float2*)(uni + (size_t)row * D_TOT + g * GCOLS + c0);

    // non-hot u-argmax (gumbel is monotone in u)
    float un0 = (c0 == hot)     ? -1.f : u.x;
    float un1 = (c0 + 1 == hot) ? -1.f : u.y;
    float uv; int ui;
    if (un0 >= un1) { uv = un0; ui = c0; } else { uv = un1; ui = c0 + 1; }
    if (!valid) { uv = -2.f; ui = 0x7FFFFFFF; }
#pragma unroll
    for (int d = 1; d < 16; d <<= 1) {
        float ov = __shfl_xor_sync(FULLM, uv, d);
        int   oi = __shfl_xor_sync(FULLM, ui, d);
        if (L.widthL > d && (ov > uv || (ov == uv && oi < ui))) { uv = ov; ui = oi; }
    }

    // fetch u at hot col from its owner lane
    const int hlane = cpToLane(hot >> 1);
    const float uh = __shfl_sync(FULLM, (hot & 1) ? u.y : u.x, hlane);

    // hot vs best-other: fast gumbel compare with precise fallback
    int win = ui;
    if (valid) {
        const float v_b = -__logf(uv + 1e-30f);
        const float v_h = -__logf(uh + 1e-30f);
        const float zb_f = qb + (-__logf(v_b + 1e-30f));
        const float zh_f = lae_fast(lc, qb) + (-__logf(v_h + 1e-30f));
        const float d = zh_f - zb_f;
        if (uv > 0.996f || uh > 0.996f || fabsf(d) < 1e-3f) {
            // precise path — bit-faithful to reference formulas
            const float gb = -logf(-logf(uv + 1e-30f) + 1e-30f);
            const float gh = -logf(-logf(uh + 1e-30f) + 1e-30f);
            const float zb = qb + gb;
            const float zh = lae_prec(lc, qb) + gh;
            win = (zh > zb) ? hot : ((zh == zb) ? min(hot, ui) : ui);
        } else {
            win = (d > 0.f) ? hot : ui;
        }
    }
    if (valid && lane == L.lbase) g_win[row * F_TOT + feat] = g * GCOLS + win;
}

// ---------------- K2: fused gather + posteriors + KL ----------------
// Block = 1024 threads (32 warps), smem = W group-block only (123 KB -> 1 CTA/SM,
// 50% occupancy). Winners/x0/t read straight from L2.
#define SMEM_K2 (D_TOT * 31 * 8)

__global__ void __launch_bounds__(1024, 1) k_fuse(
    const int* __restrict__ x0, const int* __restrict__ ts,
    const float* __restrict__ W, const float* __restrict__ bias,
    const float* __restrict__ temb, int B)
{
    extern __shared__ float2 sW2[];                 // [496][31] float2
    const int g = blockIdx.y;
    const int tid = threadIdx.x, lane = tid & 31, wid = tid >> 5;
    const int gbase = g * GCOLS;

    // stage W[:, group]
    for (int idx = tid; idx < D_TOT * 31; idx += 1024) {
        int r = idx / 31, c = idx - r * 31;
        sW2[idx] = *(const float2*)(W + (size_t)r * D_TOT + gbase + 2 * c);
    }
    __syncthreads();

    const int per = (B + gridDim.x - 1) / gridDim.x;
    const int r0 = blockIdx.x * per;
    int r1 = r0 + per; if (r1 > B) r1 = B;

    Lane L = laneLayout(lane);
    const bool valid = (L.widthL > 0);
    const int C0 = gbase + 2 * L.cp;
    const int feat = g * 5 + L.la;
    const float LOGEPS = -69.07755279f;
    const float lcT  = g_log_ca[T_STEPS - 1];
    const float l1cT = g_log_1m_ca[T_STEPS - 1];
    const float2 cs2 = *(const float2*)(g_colsum + C0);
    const float2 b2  = *(const float2*)(bias + C0);
    const float NEG = -FLT_MAX;
    const float qbT = l1cT - L.lnc;

    for (int row = r0 + wid; row < r1; row += 32) {
        const int fidx = row * F_TOT;
        const int t = __ldg(&ts[row]);
        const int wl = __ldg(&g_win[fidx + lane]);              // f = lane
        const int wh = __ldg(&g_win[fidx + 32 + (lane & 7)]);   // f = 32..39
        const int x0v = __ldg(&x0[fidx + feat]);
        const int tm1 = (t > 0) ? (t - 1) : 0;
        const float laa  = g_log_alpha[t];
        const float l1a  = g_log_1m_alpha[t];
        const float lcm  = g_log_ca[tm1];
        const float l1cm = g_log_1m_ca[tm1];
        const bool t0 = (t == 0);

        const int hot = L.sstart + x0v;
        const int c0l = 2 * L.cp;
        const bool h0 = (c0l == hot), h1 = (c0l + 1 == hot);
        const int wA = __shfl_sync(FULLM, wl, feat & 31);
        const int wB = __shfl_sync(FULLM, wh, (feat - 32) & 7);
        const int wcol = (feat < 32) ? wA : wB;
        const bool w0 = (C0 == wcol), w1 = (C0 + 1 == wcol);

        // gather sum of 40 winner rows (SMEM)
        const int wl31 = wl * 31, wh31 = wh * 31;
        float g0 = 0.f, g1 = 0.f;
#pragma unroll
        for (int f = 0; f < 32; f++) {
            int wr = __shfl_sync(FULLM, wl31, f);
            float2 v = sW2[wr + L.cp];
            g0 += v.x; g1 += v.y;
        }
#pragma unroll
        for (int f = 0; f < 8; f++) {
            int wr = __shfl_sync(FULLM, wh31, f);
            float2 v = sW2[wr + L.cp];
            g0 += v.x; g1 += v.y;
        }
        const float2 te = *(const float2*)(temb + (size_t)t * D_TOT + C0);
        const float p0 = LOGEPS * (cs2.x - g0) + b2.x + te.x;
        const float p1 = LOGEPS * (cs2.y - g1) + b2.y + te.y;

        // per-segment log-softmax
        float m = valid ? fmaxf(p0, p1) : NEG;
        m = segMax(m, L.widthL);
        float s = valid ? (__expf(p0 - m) + __expf(p1 - m)) : 0.f;
        s = segSum(s, L.widthL);
        const float lse = m + __logf(s);
        const float lh00 = p0 - lse, lh01 = p1 - lse;

        const float qb1 = l1a - L.lnc;
        const float qbm = l1cm - L.lnc;
        const float lxt0 = w0 ? 0.f : LOGEPS, lxt1 = w1 ? 0.f : LOGEPS;
        const float lx00 = h0 ? 0.f : LOGEPS, lx01 = h1 ? 0.f : LOGEPS;

        const float qo0 = lae_fast(lxt0 + laa, qb1);
        const float qo1 = lae_fast(lxt1 + laa, qb1);
        const float ev0 = t0 ? lx00 : lae_fast(lx00 + lcm, qbm);
        const float ev1 = t0 ? lx01 : lae_fast(lx01 + lcm, qbm);
        const float un0 = ev0 + qo0, un1 = ev1 + qo1;
        const float e20 = t0 ? lh00 : lae_fast(lh00 + lcm, qbm);
        const float e21 = t0 ? lh01 : lae_fast(lh01 + lcm, qbm);
        const float v20 = e20 + qo0, v21 = e21 + qo1;

        float m1 = valid ? fmaxf(un0, un1) : NEG; m1 = segMax(m1, L.widthL);
        float s1 = valid ? (__expf(un0 - m1) + __expf(un1 - m1)) : 0.f; s1 = segSum(s1, L.widthL);
        const float n1 = m1 + __logf(s1);
        float m2 = valid ? fmaxf(v20, v21) : NEG; m2 = segMax(m2, L.widthL);
        float s2 = valid ? (__expf(v20 - m2) + __expf(v21 - m2)) : 0.f; s2 = segSum(s2, L.widthL);
        const float n2 = m2 + __logf(s2);

        const float lt0 = un0 - n1, lt1 = un1 - n1;
        const float le0 = v20 - n2, le1 = v21 - n2;
        const float kl = __expf(lt0) * (lt0 - le0) + __expf(lt1) * (lt1 - le1);
        const float de = -((h0 ? le0 : 0.f) + (h1 ? le1 : 0.f));
        const float lq0 = lae_fast(lx00 + lcT, qbT);
        const float lq1 = lae_fast(lx01 + lcT, qbT);
        const float pr = __expf(lq0) * (lq0 + L.lnc) + __expf(lq1) * (lq1 + L.lnc);

        float contrib = valid ? ((t0 ? de : kl) * 1000.f + pr) : 0.f;
#pragma unroll
        for (int d = 1; d < 32; d <<= 1)
            contrib += __shfl_xor_sync(FULLM, contrib, d);
        if (lane == 0) g_part[row * GROUPS + g] = contrib;
    }
}

// ---------------- deterministic two-stage mean ----------------
__global__ void k_red1(int n) {
    __shared__ float s[1024];
    const int per = (n + 63) >> 6;
    const int b = blockIdx.x;
    int end = (b + 1) * per; if (end > n) end = n;
    float a = 0.f;
    for (int i = b * per + threadIdx.x; i < end; i += 1024) a += g_part[i];
    s[threadIdx.x] = a;
    __syncthreads();
    for (int off = 512; off > 0; off >>= 1) {
        if (threadIdx.x < off) s[threadIdx.x] += s[threadIdx.x + off];
        __syncthreads();
    }
    if (threadIdx.x == 0) g_red1[b] = s[0];
}
__global__ void k_red2(float* __restrict__ out, int B) {
    if (threadIdx.x == 0) {
        float s = 0.f;
#pragma unroll
        for (int i = 0; i < 64; i++) s += g_red1[i];
        out[0] = s / (float)B;
    }
}

// ---------------- launch ----------------
extern "C" void kernel_launch(void* const* d_in, const int* in_sizes, int n_in,
                              void* d_out, int out_size) {
    const int*   x0   = (const int*)d_in[0];
    const int*   ts   = (const int*)d_in[1];
    const float* uni  = (const float*)d_in[2];
    const float* W    = (const float*)d_in[3];
    const float* bias = (const float*)d_in[4];
    const float* temb = (const float*)d_in[5];
    float* out = (float*)d_out;
    const int B = in_sizes[1];

    cudaFuncSetAttribute(k_fuse, cudaFuncAttributeMaxDynamicSharedMemorySize, SMEM_K2);

    k_prep<<<17, 1024>>>(W);
    k_csfin<<<1, 512>>>();
    k_sample<<<B, 256>>>(x0, ts, uni);
    dim3 gridF(NTILES, GROUPS);
    k_fuse<<<gridF, 1024, SMEM_K2>>>(x0, ts, W, bias, temb, B);
    k_red1<<<64, 1024>>>(B * GROUPS);
    k_red2<<<1, 32>>>(out, B);
}

// round 5
// speedup vs baseline: 1.8822x; 1.1128x over previous
#include <cuda_runtime.h>
#include <cstdint>
#include <math.h>
#include <float.h>

#define D_TOT   496
#define F_TOT   40
#define T_STEPS 1000
#define B_MAX   32768
#define GROUPS  8
#define GCOLS   62
#define NTILES  18
#define FULLM   0xFFFFFFFFu

// ---------------- device scratch ----------------
__device__ float g_log_alpha[T_STEPS];
__device__ float g_log_1m_alpha[T_STEPS];
__device__ float g_log_ca[T_STEPS];
__device__ float g_log_1m_ca[T_STEPS];
__device__ float g_cspart[16 * D_TOT];
__device__ float g_colsum[D_TOT];
__device__ int   g_win[B_MAX * F_TOT];
__device__ float g_part[B_MAX * GROUPS];
__device__ float g_red1[64];

// ---------------- helpers ----------------
__device__ __forceinline__ float lae_prec(float a, float b) {
    float m = fmaxf(a, b), n = fminf(a, b);
    return m + log1pf(expf(n - m));
}
__device__ __forceinline__ float lae_fast(float a, float b) {
    float m = fmaxf(a, b), n = fminf(a, b);
    return m + __logf(1.0f + __expf(n - m));
}

// Lane layout: each lane owns 2 adjacent columns (one float2) of ONE feature.
// Feature sizes 2,4,8,16,32 at group-local cols [0,2),[2,6),[6,14),[14,30),[30,62).
struct Lane { int la, widthL, lbase, cp, sstart; float lnc; };
__device__ __forceinline__ Lane laneLayout(int lane) {
    Lane L;
    if (lane < 16)      { L.la=4; L.widthL=16; L.lbase=0;  L.cp=15+lane; L.sstart=30; L.lnc=3.46573590f; }
    else if (lane < 24) { L.la=3; L.widthL=8;  L.lbase=16; L.cp=lane-9;  L.sstart=14; L.lnc=2.77258872f; }
    else if (lane < 28) { L.la=2; L.widthL=4;  L.lbase=24; L.cp=lane-21; L.sstart=6;  L.lnc=2.07944154f; }
    else if (lane < 30) { L.la=1; L.widthL=2;  L.lbase=28; L.cp=lane-27; L.sstart=2;  L.lnc=1.38629436f; }
    else if (lane == 30){ L.la=0; L.widthL=1;  L.lbase=30; L.cp=0;       L.sstart=0;  L.lnc=0.69314718f; }
    else                { L.la=0; L.widthL=0;  L.lbase=31; L.cp=0;       L.sstart=0;  L.lnc=0.69314718f; }
    return L;
}
__device__ __forceinline__ int cpToLane(int cp) {
    return (cp >= 15) ? cp - 15 : (cp >= 7) ? cp + 9 : (cp >= 3) ? cp + 21
         : (cp >= 1) ? cp + 27 : 30;
}
__device__ __forceinline__ float segMax(float v, int widthL) {
#pragma unroll
    for (int d = 1; d < 16; d <<= 1) {
        float o = __shfl_xor_sync(FULLM, v, d);
        if (widthL > d) v = fmaxf(v, o);
    }
    return v;
}
__device__ __forceinline__ float segSum(float v, int widthL) {
#pragma unroll
    for (int d = 1; d < 16; d <<= 1) {
        float o = __shfl_xor_sync(FULLM, v, d);
        if (widthL > d) v += o;
    }
    return v;
}

// ---------------- prologue ----------------
__global__ void k_prep(const float* __restrict__ W) {
    int tid = threadIdx.x;
    if (blockIdx.x == 0) {
        __shared__ double sd[1024];
        double lad = 0.0;
        if (tid < T_STEPS) {
            double beta = 1e-4 + (double)tid * ((0.02 - 1e-4) / 999.0);
            double alpha = 1.0 - beta;
            lad = log(alpha);
            g_log_alpha[tid] = (float)lad;
            g_log_1m_alpha[tid] = (float)log(beta);
        }
        sd[tid] = lad;
        __syncthreads();
        for (int off = 1; off < 1024; off <<= 1) {
            double add = (tid >= off) ? sd[tid - off] : 0.0;
            __syncthreads();
            sd[tid] += add;
            __syncthreads();
        }
        if (tid < T_STEPS) {
            double cum = sd[tid];
            g_log_ca[tid] = (float)cum;
            g_log_1m_ca[tid] = (float)log(-expm1(cum));
        }
    } else {
        int p = blockIdx.x - 1;
        int r0 = p * 31;
        if (tid < D_TOT) {
            float acc = 0.f;
#pragma unroll
            for (int r = 0; r < 31; r++)
                acc += W[(r0 + r) * D_TOT + tid];
            g_cspart[p * D_TOT + tid] = acc;
        }
    }
}
__global__ void k_csfin() {
    int j = threadIdx.x;
    if (j < D_TOT) {
        float s = 0.f;
#pragma unroll
        for (int p = 0; p < 16; p++) s += g_cspart[p * D_TOT + j];
        g_colsum[j] = s;
    }
}

// ---------------- K1: persistent Gumbel-max sampler ----------------
__global__ void __launch_bounds__(1024) k_sample(
    const int* __restrict__ x0, const int* __restrict__ ts,
    const float* __restrict__ uni, int B)
{
    const int lane = threadIdx.x & 31;
    Lane L = laneLayout(lane);
    const bool valid = (L.widthL > 0);
    const int c0 = 2 * L.cp;
    const int gw0 = (blockIdx.x * 1024 + threadIdx.x) >> 5;
    const int nw = (gridDim.x * 1024) >> 5;
    const int ntask = B * GROUPS;

    for (int task = gw0; task < ntask; task += nw) {
        const int row = task >> 3, g = task & 7;
        const int t = __ldg(&ts[row]);
        const float lc = g_log_ca[t], l1c = g_log_1m_ca[t];
        const int feat = g * 5 + L.la;
        const int x0v = valid ? __ldg(&x0[row * F_TOT + feat]) : 0;
        const int hot = L.sstart + x0v;
        const float qb = l1c - L.lnc;

        float2 u = make_float2(0.f, 0.f);
        if (valid) u = *(const float2*)(uni + (size_t)row * D_TOT + g * GCOLS + c0);

        // non-hot u-argmax (gumbel monotone in u)
        float un0 = (c0 == hot)     ? -1.f : u.x;
        float un1 = (c0 + 1 == hot) ? -1.f : u.y;
        float uv; int ui;
        if (un0 >= un1) { uv = un0; ui = c0; } else { uv = un1; ui = c0 + 1; }
        if (!valid) { uv = -2.f; ui = 0x7FFFFFFF; }
#pragma unroll
        for (int d = 1; d < 16; d <<= 1) {
            float ov = __shfl_xor_sync(FULLM, uv, d);
            int   oi = __shfl_xor_sync(FULLM, ui, d);
            if (L.widthL > d && (ov > uv || (ov == uv && oi < ui))) { uv = ov; ui = oi; }
        }

        const int hlane = cpToLane(hot >> 1);
        const float uh = __shfl_sync(FULLM, (hot & 1) ? u.y : u.x, hlane);

        int win = ui;
        if (valid) {
            const float v_b = -__logf(uv + 1e-30f);
            const float v_h = -__logf(uh + 1e-30f);
            const float zb_f = qb + (-__logf(v_b + 1e-30f));
            const float zh_f = lae_fast(lc, qb) + (-__logf(v_h + 1e-30f));
            const float d = zh_f - zb_f;
            if (uv > 0.996f || uh > 0.996f || fabsf(d) < 1e-3f) {
                const float gb = -logf(-logf(uv + 1e-30f) + 1e-30f);
                const float gh = -logf(-logf(uh + 1e-30f) + 1e-30f);
                const float zb = qb + gb;
                const float zh = lae_prec(lc, qb) + gh;
                win = (zh > zb) ? hot : ((zh == zb) ? min(hot, ui) : ui);
            } else {
                win = (d > 0.f) ? hot : ui;
            }
        }
        if (valid && lane == L.lbase) g_win[row * F_TOT + feat] = g * GCOLS + win;
    }
}

// ---------------- K2: fused gather + posteriors + KL ----------------
#define SMEM_K2 (D_TOT * 31 * 8)

__global__ void __launch_bounds__(1024, 1) k_fuse(
    const int* __restrict__ x0, const int* __restrict__ ts,
    const float* __restrict__ W, const float* __restrict__ bias,
    const float* __restrict__ temb, int B)
{
    extern __shared__ float2 sW2[];                 // [496][31] float2
    const int g = blockIdx.y;
    const int tid = threadIdx.x, lane = tid & 31, wid = tid >> 5;
    const int gbase = g * GCOLS;

    for (int idx = tid; idx < D_TOT * 31; idx += 1024) {
        int r = idx / 31, c = idx - r * 31;
        sW2[idx] = *(const float2*)(W + (size_t)r * D_TOT + gbase + 2 * c);
    }
    __syncthreads();

    const int per = (B + gridDim.x - 1) / gridDim.x;
    const int r0 = blockIdx.x * per;
    int r1 = r0 + per; if (r1 > B) r1 = B;

    Lane L = laneLayout(lane);
    const bool valid = (L.widthL > 0);
    const int C0 = gbase + 2 * L.cp;
    const int feat = g * 5 + L.la;
    const float LOGEPS = -69.07755279f;
    const float2 cs2 = *(const float2*)(g_colsum + C0);
    const float2 b2  = *(const float2*)(bias + C0);
    const float NEG = -FLT_MAX;

    // per-lane constants: kl_prior terms (t = T-1 fixed)
    const float lcT  = g_log_ca[T_STEPS - 1];
    const float l1cT = g_log_1m_ca[T_STEPS - 1];
    const float qbT  = l1cT - L.lnc;
    const float lqh  = lae_fast(lcT, qbT);
    const float prh  = __expf(lqh) * (lqh + L.lnc);
    const float prc  = __expf(qbT) * (qbT + L.lnc);

    // shared-base for packed gather
    unsigned int sbase;
    asm("{ .reg .u64 t; cvta.to.shared.u64 t, %1; cvt.u32.u64 %0, t; }"
        : "=r"(sbase) : "l"((void*)sW2));
    const unsigned int aoff = sbase + (unsigned int)L.cp * 8u;

    for (int row = r0 + wid; row < r1; row += 32) {
        const int fidx = row * F_TOT;
        const int t = __ldg(&ts[row]);
        const int wl = __ldg(&g_win[fidx + lane]);
        const int wh = __ldg(&g_win[fidx + 32 + (lane & 7)]);
        const int x0v = __ldg(&x0[fidx + feat]);
        const int tm1 = (t > 0) ? (t - 1) : 0;
        const float laa  = g_log_alpha[t];
        const float l1a  = g_log_1m_alpha[t];
        const float lcm  = g_log_ca[tm1];
        const float l1cm = g_log_1m_ca[tm1];
        const bool t0 = (t == 0);

        const int hot = L.sstart + x0v;
        const int c0l = 2 * L.cp;
        const bool h0 = (c0l == hot), h1 = (c0l + 1 == hot);
        const int wA = __shfl_sync(FULLM, wl, feat & 31);
        const int wB = __shfl_sync(FULLM, wh, (feat - 32) & 7);
        const int wcol = (feat < 32) ? wA : wB;
        const bool w0 = (C0 == wcol), w1 = (C0 + 1 == wcol);

        // ---- gather: packed f32x2 sum of 40 winner rows (SMEM) ----
        const int wlB = wl * 248, whB = wh * 248;   // byte offsets of winner rows
        unsigned long long acc = 0ULL;
#pragma unroll
        for (int f = 0; f < 32; f++) {
            int o = __shfl_sync(FULLM, wlB, f);
            unsigned long long v;
            asm("ld.shared.b64 %0, [%1];" : "=l"(v) : "r"(aoff + (unsigned int)o));
            asm("add.rn.f32x2 %0, %0, %1;" : "+l"(acc) : "l"(v));
        }
#pragma unroll
        for (int f = 0; f < 8; f++) {
            int o = __shfl_sync(FULLM, whB, f);
            unsigned long long v;
            asm("ld.shared.b64 %0, [%1];" : "=l"(v) : "r"(aoff + (unsigned int)o));
            asm("add.rn.f32x2 %0, %0, %1;" : "+l"(acc) : "l"(v));
        }
        float g0, g1;
        asm("mov.b64 {%0, %1}, %2;" : "=f"(g0), "=f"(g1) : "l"(acc));

        const float2 te = *(const float2*)(temb + (size_t)t * D_TOT + C0);
        const float p0 = LOGEPS * (cs2.x - g0) + b2.x + te.x;
        const float p1 = LOGEPS * (cs2.y - g1) + b2.y + te.y;

        // per-segment log-softmax of pred (keep max pass: pred can be large +)
        float m = valid ? fmaxf(p0, p1) : NEG;
        m = segMax(m, L.widthL);
        float s = valid ? (__expf(p0 - m) + __expf(p1 - m)) : 0.f;
        s = segSum(s, L.widthL);
        const float lse = m + __logf(s);
        const float lh00 = p0 - lse, lh01 = p1 - lse;

        // sparse-select logaddexp: cold branch is exactly qb in fp32
        const float qb1 = l1a - L.lnc;
        const float qbm = l1cm - L.lnc;
        const float qow = lae_fast(laa, qb1);               // winner-col q_one value
        const float evh = t0 ? 0.f : lae_fast(lcm, qbm);    // hot-col ev value
        const float evc = t0 ? LOGEPS : qbm;                // cold ev value

        const float qo0 = w0 ? qow : qb1, qo1 = w1 ? qow : qb1;
        const float ev0 = h0 ? evh : evc, ev1 = h1 ? evh : evc;
        const float un0 = ev0 + qo0, un1 = ev1 + qo1;

        const float e20 = t0 ? lh00 : lae_fast(lh00 + lcm, qbm);
        const float e21 = t0 ? lh01 : lae_fast(lh01 + lcm, qbm);
        const float v20 = e20 + qo0, v21 = e21 + qo1;

        // posterior normalizations WITHOUT max pass (un >= -82 provably)
        const float eu0 = valid ? __expf(un0) : 0.f;
        const float eu1 = valid ? __expf(un1) : 0.f;
        const float ew0 = valid ? __expf(v20) : 0.f;
        const float ew1 = valid ? __expf(v21) : 0.f;
        const float s1 = segSum(eu0 + eu1, L.widthL);
        const float s2 = segSum(ew0 + ew1, L.widthL);
        const float n1 = __logf(s1), n2 = __logf(s2);
        const float dn = n2 - n1;
        const float inv1 = __fdividef(1.f, s1);

        const float klL = (eu0 * (un0 - v20 + dn) + eu1 * (un1 - v21 + dn)) * inv1;
        const float deL = (h0 ? (n2 - v20) : 0.f) + (h1 ? (n2 - v21) : 0.f);
        const float prL = (h0 ? prh : prc) + (h1 ? prh : prc);

        float contrib = valid ? ((t0 ? deL : klL) * 1000.f + prL) : 0.f;
#pragma unroll
        for (int d = 1; d < 32; d <<= 1)
            contrib += __shfl_xor_sync(FULLM, contrib, d);
        if (lane == 0) g_part[row * GROUPS + g] = contrib;
    }
}

// ---------------- deterministic two-stage mean ----------------
__global__ void k_red1(int n) {
    __shared__ float s[1024];
    const int per = (n + 63) >> 6;
    const int b = blockIdx.x;
    int end = (b + 1) * per; if (end > n) end = n;
    float a = 0.f;
    for (int i = b * per + threadIdx.x; i < end; i += 1024) a += g_part[i];
    s[threadIdx.x] = a;
    __syncthreads();
    for (int off = 512; off > 0; off >>= 1) {
        if (threadIdx.x < off) s[threadIdx.x] += s[threadIdx.x + off];
        __syncthreads();
    }
    if (threadIdx.x == 0) g_red1[b] = s[0];
}
__global__ void k_red2(float* __restrict__ out, int B) {
    if (threadIdx.x == 0) {
        float s = 0.f;
#pragma unroll
        for (int i = 0; i < 64; i++) s += g_red1[i];
        out[0] = s / (float)B;
    }
}

// ---------------- launch ----------------
extern "C" void kernel_launch(void* const* d_in, const int* in_sizes, int n_in,
                              void* d_out, int out_size) {
    const int*   x0   = (const int*)d_in[0];
    const int*   ts   = (const int*)d_in[1];
    const float* uni  = (const float*)d_in[2];
    const float* W    = (const float*)d_in[3];
    const float* bias = (const float*)d_in[4];
    const float* temb = (const float*)d_in[5];
    float* out = (float*)d_out;
    const int B = in_sizes[1];

    cudaFuncSetAttribute(k_fuse, cudaFuncAttributeMaxDynamicSharedMemorySize, SMEM_K2);

    k_prep<<<17, 1024>>>(W);
    k_csfin<<<1, 512>>>();
    k_sample<<<296, 1024>>>(x0, ts, uni, B);
    dim3 gridF(NTILES, GROUPS);
    k_fuse<<<gridF, 1024, SMEM_K2>>>(x0, ts, W, bias, temb, B);
    k_red1<<<64, 1024>>>(B * GROUPS);
    k_red2<<<1, 32>>>(out, B);
}

// round 6
// speedup vs baseline: 2.3804x; 1.2647x over previous
#include <cuda_runtime.h>
#include <cuda_fp16.h>
#include <cstdint>
#include <math.h>
#include <float.h>

#define D_TOT   496
#define F_TOT   40
#define T_STEPS 1000
#define B_MAX   32768
#define GROUPS  8
#define GCOLS   62
#define NTILES  18
#define CHUNK   128
#define FULLM   0xFFFFFFFFu

// ---------------- device scratch ----------------
__device__ float  g_log_ca[T_STEPS];
__device__ float  g_log_1m_ca[T_STEPS];
__device__ float2 g_ca2[T_STEPS];     // (log_ca[t], log_1m_ca[t])
__device__ float4 g_tab4[T_STEPS];    // (log_alpha, log_1m_alpha, log_ca[t-1], log_1m_ca[t-1])
__device__ int    g_win[B_MAX * F_TOT];
__device__ float  g_part[B_MAX * GROUPS];
__device__ float  g_red1[64];

// ---------------- helpers ----------------
__device__ __forceinline__ float lae_prec(float a, float b) {
    float m = fmaxf(a, b), n = fminf(a, b);
    return m + log1pf(expf(n - m));
}
__device__ __forceinline__ float lae_fast(float a, float b) {
    float m = fmaxf(a, b), n = fminf(a, b);
    return m + __logf(1.0f + __expf(n - m));
}

// Lane layout: each lane owns 2 adjacent columns (one pair) of ONE feature.
// Feature sizes 2,4,8,16,32 at group-local cols [0,2),[2,6),[6,14),[14,30),[30,62).
struct Lane { int la, widthL, lbase, cp, sstart; float lnc; };
__device__ __forceinline__ Lane laneLayout(int lane) {
    Lane L;
    if (lane < 16)      { L.la=4; L.widthL=16; L.lbase=0;  L.cp=15+lane; L.sstart=30; L.lnc=3.46573590f; }
    else if (lane < 24) { L.la=3; L.widthL=8;  L.lbase=16; L.cp=lane-9;  L.sstart=14; L.lnc=2.77258872f; }
    else if (lane < 28) { L.la=2; L.widthL=4;  L.lbase=24; L.cp=lane-21; L.sstart=6;  L.lnc=2.07944154f; }
    else if (lane < 30) { L.la=1; L.widthL=2;  L.lbase=28; L.cp=lane-27; L.sstart=2;  L.lnc=1.38629436f; }
    else if (lane == 30){ L.la=0; L.widthL=1;  L.lbase=30; L.cp=0;       L.sstart=0;  L.lnc=0.69314718f; }
    else                { L.la=0; L.widthL=0;  L.lbase=31; L.cp=0;       L.sstart=0;  L.lnc=0.69314718f; }
    return L;
}
__device__ __forceinline__ int cpToLane(int cp) {
    return (cp >= 15) ? cp - 15 : (cp >= 7) ? cp + 9 : (cp >= 3) ? cp + 21
         : (cp >= 1) ? cp + 27 : 30;
}
__device__ __forceinline__ float segMax(float v, int widthL) {
#pragma unroll
    for (int d = 1; d < 16; d <<= 1) {
        float o = __shfl_xor_sync(FULLM, v, d);
        if (widthL > d) v = fmaxf(v, o);
    }
    return v;
}
__device__ __forceinline__ float segSum(float v, int widthL) {
#pragma unroll
    for (int d = 1; d < 16; d <<= 1) {
        float o = __shfl_xor_sync(FULLM, v, d);
        if (widthL > d) v += o;
    }
    return v;
}

// ---------------- prologue: tables via fp32 + double-single scan ----------------
__global__ void __launch_bounds__(1024) k_prep() {
    __shared__ float shi[1024], slo[1024], sl1c[1024];
    const int tid = threadIdx.x;
    float la = 0.f, l1b = 0.f;
    if (tid < T_STEPS) {
        double beta = 1e-4 + (double)tid * ((0.02 - 1e-4) / 999.0);
        float betaf = (float)beta;
        la  = log1pf(-betaf);        // log(alpha_t)
        l1b = logf(betaf);           // log(1 - alpha_t) = log(beta_t)
    }
    shi[tid] = la; slo[tid] = 0.f;
    __syncthreads();
    // Hillis-Steele inclusive scan in double-single (compensated) fp32
    for (int off = 1; off < 1024; off <<= 1) {
        float ahi = (tid >= off) ? shi[tid - off] : 0.f;
        float alo = (tid >= off) ? slo[tid - off] : 0.f;
        __syncthreads();
        float x = shi[tid];
        float s = x + ahi;
        float bb = s - x;
        float err = (x - (s - bb)) + (ahi - bb);
        float lo = err + slo[tid] + alo;
        float hi2 = s + lo;
        lo = lo - (hi2 - s);
        shi[tid] = hi2; slo[tid] = lo;
        __syncthreads();
    }
    float cum = 0.f, l1c = 0.f;
    if (tid < T_STEPS) {
        cum = shi[tid];
        l1c = logf(-expm1f(cum));    // log(1 - cumprod(alpha))
        g_log_ca[tid] = cum;
        g_log_1m_ca[tid] = l1c;
        g_ca2[tid] = make_float2(cum, l1c);
    }
    sl1c[tid] = l1c;
    __syncthreads();
    if (tid < T_STEPS) {
        int tm1 = (tid > 0) ? tid - 1 : 0;
        g_tab4[tid] = make_float4(la, l1b, shi[tm1], sl1c[tm1]);
    }
}

// ---------------- K1: persistent Gumbel-max sampler ----------------
__global__ void __launch_bounds__(1024) k_sample(
    const int* __restrict__ x0, const int* __restrict__ ts,
    const float* __restrict__ uni, int B)
{
    const int lane = threadIdx.x & 31;
    Lane L = laneLayout(lane);
    const bool valid = (L.widthL > 0);
    const int c0 = 2 * L.cp;
    const int gw0 = (blockIdx.x * 1024 + threadIdx.x) >> 5;
    const int nw = (gridDim.x * 1024) >> 5;
    const int ntask = B * GROUPS;

    for (int task = gw0; task < ntask; task += nw) {
        const int row = task >> 3, g = task & 7;
        const int t = __ldg(&ts[row]);
        const float2 ca = __ldg(&g_ca2[t]);
        const float lc = ca.x, l1c = ca.y;
        const int feat = g * 5 + L.la;
        const int x0v = valid ? __ldg(&x0[row * F_TOT + feat]) : 0;
        const int hot = L.sstart + x0v;
        const float qb = l1c - L.lnc;

        float2 u = make_float2(0.f, 0.f);
        if (valid) u = *(const float2*)(uni + (size_t)row * D_TOT + g * GCOLS + c0);

        // non-hot u-argmax (gumbel monotone in u)
        float un0 = (c0 == hot)     ? -1.f : u.x;
        float un1 = (c0 + 1 == hot) ? -1.f : u.y;
        float uv; int ui;
        if (un0 >= un1) { uv = un0; ui = c0; } else { uv = un1; ui = c0 + 1; }
        if (!valid) { uv = -2.f; ui = 0x7FFFFFFF; }
#pragma unroll
        for (int d = 1; d < 16; d <<= 1) {
            float ov = __shfl_xor_sync(FULLM, uv, d);
            int   oi = __shfl_xor_sync(FULLM, ui, d);
            if (L.widthL > d && (ov > uv || (ov == uv && oi < ui))) { uv = ov; ui = oi; }
        }

        const int hlane = cpToLane(hot >> 1);
        const float uh = __shfl_sync(FULLM, (hot & 1) ? u.y : u.x, hlane);

        int win = ui;
        if (valid) {
            const float v_b = -__logf(uv + 1e-30f);
            const float v_h = -__logf(uh + 1e-30f);
            const float zb_f = qb + (-__logf(v_b + 1e-30f));
            const float zh_f = lae_fast(lc, qb) + (-__logf(v_h + 1e-30f));
            const float d = zh_f - zb_f;
            if (uv > 0.996f || uh > 0.996f || fabsf(d) < 1e-3f) {
                const float gb = -logf(-logf(uv + 1e-30f) + 1e-30f);
                const float gh = -logf(-logf(uh + 1e-30f) + 1e-30f);
                const float zb = qb + gb;
                const float zh = lae_prec(lc, qb) + gh;
                win = (zh > zb) ? hot : ((zh == zb) ? min(hot, ui) : ui);
            } else {
                win = (d > 0.f) ? hot : ui;
            }
        }
        if (valid && lane == L.lbase) g_win[row * F_TOT + feat] = g * GCOLS + win;
    }
}

// ---------------- K2: fused gather + posteriors + KL (fp16 W, staged offsets) ----------------
// smem layout (bytes):
//   [0, 61504)          sW    half2[496*31]   (W group-block, fp16)
//   [61504, 81984)      sOff  int[CHUNK*40]   (winner byte-offsets; union w/ colsum scratch)
//   [81984, 82232)      sCs   float2[31]      (fp32 colsum of group cols)
#define SMEM_OFF 61504
#define SMEM_CS  81984
#define SMEM_K2  (SMEM_CS + 31 * 8 + 8)

__global__ void __launch_bounds__(1024, 1) k_fuse(
    const int* __restrict__ x0, const int* __restrict__ ts,
    const float* __restrict__ W, const float* __restrict__ bias,
    const float* __restrict__ temb, int B)
{
    extern __shared__ char smem[];
    half2*  sW   = (half2*)smem;
    int*    sOff = (int*)(smem + SMEM_OFF);
    float2* sScr = (float2*)(smem + SMEM_OFF);   // staging-time union
    float2* sCs  = (float2*)(smem + SMEM_CS);

    const int g = blockIdx.y;
    const int tid = threadIdx.x, lane = tid & 31, wid = tid >> 5;
    const int gbase = g * GCOLS;

    // ---- stage W -> fp16 smem, accumulate exact fp32 colsum ----
    float2 acc = make_float2(0.f, 0.f);
    for (int r = wid; r < D_TOT; r += 32) {
        if (lane < 31) {
            float2 v = *(const float2*)(W + (size_t)r * D_TOT + gbase + 2 * lane);
            acc.x += v.x; acc.y += v.y;
            sW[r * 31 + lane] = __floats2half2_rn(v.x, v.y);
        }
    }
    if (lane < 31) sScr[wid * 31 + lane] = acc;
    __syncthreads();
    if (tid < 31) {
        float2 s = make_float2(0.f, 0.f);
#pragma unroll
        for (int w2 = 0; w2 < 32; w2++) { float2 a = sScr[w2 * 31 + tid]; s.x += a.x; s.y += a.y; }
        sCs[tid] = s;
    }
    __syncthreads();

    Lane L = laneLayout(lane);
    const bool valid = (L.widthL > 0);
    const float2 cs2 = sCs[L.cp];

    const int per = (B + gridDim.x - 1) / gridDim.x;
    const int r0 = blockIdx.x * per;
    const int r1 = min(r0 + per, B);

    const int C0 = gbase + 2 * L.cp;
    const int feat = g * 5 + L.la;
    const float LOGEPS = -69.07755279f;
    const float2 b2 = *(const float2*)(bias + C0);
    const float NEG = -FLT_MAX;

    // kl_prior per-lane constants (t = T-1 fixed)
    const float2 caT = __ldg(&g_ca2[T_STEPS - 1]);
    const float qbT = caT.y - L.lnc;
    const float lqh = lae_fast(caT.x, qbT);
    const float prh = __expf(lqh) * (lqh + L.lnc);
    const float prc = __expf(qbT) * (qbT + L.lnc);

    const int offC0 = C0 * 124, offC1 = offC0 + 124;
    const char* sWb = smem;
    const int cpb = L.cp * 4;

    for (int cr = r0; cr < r1; cr += CHUNK) {
        __syncthreads();                         // protect sOff reuse
        const int nrows = min(CHUNK, r1 - cr);
        for (int i = tid; i < nrows * F_TOT; i += 1024)
            sOff[i] = __ldg(&g_win[cr * F_TOT + i]) * 124;
        __syncthreads();

        for (int rl = wid; rl < nrows; rl += 32) {
            const int row = cr + rl;
            const int t = __ldg(&ts[row]);
            const float4 tb = __ldg(&g_tab4[t]);    // laa, l1a, lcm, l1cm
            const bool t0 = (t == 0);
            const int x0v = __ldg(&x0[row * F_TOT + feat]);
            const int hot = L.sstart + x0v;
            const bool h0 = (2 * L.cp == hot), h1 = (2 * L.cp + 1 == hot);
            const int myoff = sOff[rl * F_TOT + feat];
            const bool w0 = (myoff == offC0), w1 = (myoff == offC1);

            // ---- gather: 40 fp16 winner rows, HADD2 sub-sums of 4 ----
            const int4* op = (const int4*)(sOff + rl * F_TOT);
            float gx = 0.f, gy = 0.f;
#pragma unroll
            for (int q = 0; q < 10; q++) {
                int4 o = op[q];
                half2 a = *(const half2*)(sWb + o.x + cpb);
                half2 b = *(const half2*)(sWb + o.y + cpb);
                half2 c = *(const half2*)(sWb + o.z + cpb);
                half2 d = *(const half2*)(sWb + o.w + cpb);
                half2 s4 = __hadd2(__hadd2(a, b), __hadd2(c, d));
                float2 w2 = __half22float2(s4);
                gx += w2.x; gy += w2.y;
            }
            const float2 te = *(const float2*)(temb + (size_t)t * D_TOT + C0);
            const float p0 = LOGEPS * (cs2.x - gx) + b2.x + te.x;
            const float p1 = LOGEPS * (cs2.y - gy) + b2.y + te.y;

            // per-segment log-softmax of pred
            float m = valid ? fmaxf(p0, p1) : NEG;
            m = segMax(m, L.widthL);
            float s = valid ? (__expf(p0 - m) + __expf(p1 - m)) : 0.f;
            s = segSum(s, L.widthL);
            const float lse = m + __logf(s);
            const float lh00 = p0 - lse, lh01 = p1 - lse;

            // sparse-select logaddexp (cold branch exactly qb in fp32)
            const float qb1 = tb.y - L.lnc;
            const float qbm = tb.w - L.lnc;
            const float qow = lae_fast(tb.x, qb1);
            const float evh = t0 ? 0.f : lae_fast(tb.z, qbm);
            const float evc = t0 ? LOGEPS : qbm;

            const float qo0 = w0 ? qow : qb1, qo1 = w1 ? qow : qb1;
            const float ev0 = h0 ? evh : evc, ev1 = h1 ? evh : evc;
            const float un0 = ev0 + qo0, un1 = ev1 + qo1;

            const float e20 = t0 ? lh00 : lae_fast(lh00 + tb.z, qbm);
            const float e21 = t0 ? lh01 : lae_fast(lh01 + tb.z, qbm);
            const float v20 = e20 + qo0, v21 = e21 + qo1;

            // maxless posterior normalizations (un bounded below ~-82)
            const float eu0 = valid ? __expf(un0) : 0.f;
            const float eu1 = valid ? __expf(un1) : 0.f;
            const float ew0 = valid ? __expf(v20) : 0.f;
            const float ew1 = valid ? __expf(v21) : 0.f;
            const float s1 = segSum(eu0 + eu1, L.widthL);
            const float s2 = segSum(ew0 + ew1, L.widthL);
            const float n1 = __logf(s1), n2 = __logf(s2);
            const float dn = n2 - n1;
            const float inv1 = __fdividef(1.f, s1);

            const float klL = (eu0 * (un0 - v20 + dn) + eu1 * (un1 - v21 + dn)) * inv1;
            const float deL = (h0 ? (n2 - v20) : 0.f) + (h1 ? (n2 - v21) : 0.f);
            const float prL = (h0 ? prh : prc) + (h1 ? prh : prc);

            float contrib = valid ? ((t0 ? deL : klL) * 1000.f + prL) : 0.f;
#pragma unroll
            for (int d = 1; d < 32; d <<= 1)
                contrib += __shfl_xor_sync(FULLM, contrib, d);
            if (lane == 0) g_part[row * GROUPS + g] = contrib;
        }
    }
}

// ---------------- deterministic two-stage mean ----------------
__global__ void k_red1(int n) {
    __shared__ float s[1024];
    const int per = (n + 63) >> 6;
    const int b = blockIdx.x;
    int end = (b + 1) * per; if (end > n) end = n;
    float a = 0.f;
    for (int i = b * per + threadIdx.x; i < end; i += 1024) a += g_part[i];
    s[threadIdx.x] = a;
    __syncthreads();
    for (int off = 512; off > 0; off >>= 1) {
        if (threadIdx.x < off) s[threadIdx.x] += s[threadIdx.x + off];
        __syncthreads();
    }
    if (threadIdx.x == 0) g_red1[b] = s[0];
}
__global__ void k_red2(float* __restrict__ out, int B) {
    if (threadIdx.x == 0) {
        float s = 0.f;
#pragma unroll
        for (int i = 0; i < 64; i++) s += g_red1[i];
        out[0] = s / (float)B;
    }
}

// ---------------- launch ----------------
extern "C" void kernel_launch(void* const* d_in, const int* in_sizes, int n_in,
                              void* d_out, int out_size) {
    const int*   x0   = (const int*)d_in[0];
    const int*   ts   = (const int*)d_in[1];
    const float* uni  = (const float*)d_in[2];
    const float* W    = (const float*)d_in[3];
    const float* bias = (const float*)d_in[4];
    const float* temb = (const float*)d_in[5];
    float* out = (float*)d_out;
    const int B = in_sizes[1];

    cudaFuncSetAttribute(k_fuse, cudaFuncAttributeMaxDynamicSharedMemorySize, SMEM_K2);

    k_prep<<<1, 1024>>>();
    k_sample<<<296, 1024>>>(x0, ts, uni, B);
    dim3 gridF(NTILES, GROUPS);
    k_fuse<<<gridF, 1024, SMEM_K2>>>(x0, ts, W, bias, temb, B);
    k_red1<<<64, 1024>>>(B * GROUPS);
    k_red2<<<1, 32>>>(out, B);
}

// round 7
// speedup vs baseline: 2.4676x; 1.0366x over previous
#include <cuda_runtime.h>
#include <cuda_fp16.h>
#include <cstdint>
#include <math.h>
#include <float.h>

#define D_TOT   496
#define F_TOT   40
#define T_STEPS 1000
#define B_MAX   32768
#define GROUPS  8
#define GCOLS   62
#define NTILES  36
#define CHUNK   128
#define FULLM   0xFFFFFFFFu

// ---------------- device scratch ----------------
__device__ float  g_log_ca[T_STEPS];
__device__ float  g_log_1m_ca[T_STEPS];
__device__ float2 g_ca2[T_STEPS];     // (log_ca[t], log_1m_ca[t])
__device__ float4 g_tab4[T_STEPS];    // (log_alpha, log_1m_alpha, log_ca[t-1], log_1m_ca[t-1])
__device__ int    g_win[B_MAX * F_TOT];
__device__ float  g_part[NTILES * GROUPS * 16];
__device__ float  g_red1[64];

// ---------------- helpers ----------------
__device__ __forceinline__ float lae_prec(float a, float b) {
    float m = fmaxf(a, b), n = fminf(a, b);
    return m + log1pf(expf(n - m));
}
__device__ __forceinline__ float lae_fast(float a, float b) {
    float m = fmaxf(a, b), n = fminf(a, b);
    return m + __logf(1.0f + __expf(n - m));
}

// Lane layout: each lane owns 2 adjacent columns (one pair) of ONE feature.
// Feature sizes 2,4,8,16,32 at group-local cols [0,2),[2,6),[6,14),[14,30),[30,62).
struct Lane { int la, widthL, lbase, cp, sstart; float lnc; };
__device__ __forceinline__ Lane laneLayout(int lane) {
    Lane L;
    if (lane < 16)      { L.la=4; L.widthL=16; L.lbase=0;  L.cp=15+lane; L.sstart=30; L.lnc=3.46573590f; }
    else if (lane < 24) { L.la=3; L.widthL=8;  L.lbase=16; L.cp=lane-9;  L.sstart=14; L.lnc=2.77258872f; }
    else if (lane < 28) { L.la=2; L.widthL=4;  L.lbase=24; L.cp=lane-21; L.sstart=6;  L.lnc=2.07944154f; }
    else if (lane < 30) { L.la=1; L.widthL=2;  L.lbase=28; L.cp=lane-27; L.sstart=2;  L.lnc=1.38629436f; }
    else if (lane == 30){ L.la=0; L.widthL=1;  L.lbase=30; L.cp=0;       L.sstart=0;  L.lnc=0.69314718f; }
    else                { L.la=0; L.widthL=0;  L.lbase=31; L.cp=0;       L.sstart=0;  L.lnc=0.69314718f; }
    return L;
}
__device__ __forceinline__ int cpToLane(int cp) {
    return (cp >= 15) ? cp - 15 : (cp >= 7) ? cp + 9 : (cp >= 3) ? cp + 21
         : (cp >= 1) ? cp + 27 : 30;
}
__device__ __forceinline__ float segMax(float v, int widthL) {
#pragma unroll
    for (int d = 1; d < 16; d <<= 1) {
        float o = __shfl_xor_sync(FULLM, v, d);
        if (widthL > d) v = fmaxf(v, o);
    }
    return v;
}
__device__ __forceinline__ float segSum(float v, int widthL) {
#pragma unroll
    for (int d = 1; d < 16; d <<= 1) {
        float o = __shfl_xor_sync(FULLM, v, d);
        if (widthL > d) v += o;
    }
    return v;
}

// ---------------- prologue: tables via fp32 + double-single scan ----------------
__global__ void __launch_bounds__(1024) k_prep() {
    __shared__ float shi[1024], slo[1024], sl1c[1024];
    const int tid = threadIdx.x;
    float la = 0.f, l1b = 0.f;
    if (tid < T_STEPS) {
        double beta = 1e-4 + (double)tid * ((0.02 - 1e-4) / 999.0);
        float betaf = (float)beta;
        la  = log1pf(-betaf);
        l1b = logf(betaf);
    }
    shi[tid] = la; slo[tid] = 0.f;
    __syncthreads();
    for (int off = 1; off < 1024; off <<= 1) {
        float ahi = (tid >= off) ? shi[tid - off] : 0.f;
        float alo = (tid >= off) ? slo[tid - off] : 0.f;
        __syncthreads();
        float x = shi[tid];
        float s = x + ahi;
        float bb = s - x;
        float err = (x - (s - bb)) + (ahi - bb);
        float lo = err + slo[tid] + alo;
        float hi2 = s + lo;
        lo = lo - (hi2 - s);
        shi[tid] = hi2; slo[tid] = lo;
        __syncthreads();
    }
    float cum = 0.f, l1c = 0.f;
    if (tid < T_STEPS) {
        cum = shi[tid];
        l1c = logf(-expm1f(cum));
        g_log_ca[tid] = cum;
        g_log_1m_ca[tid] = l1c;
        g_ca2[tid] = make_float2(cum, l1c);
    }
    sl1c[tid] = l1c;
    __syncthreads();
    if (tid < T_STEPS) {
        int tm1 = (tid > 0) ? tid - 1 : 0;
        g_tab4[tid] = make_float4(la, l1b, shi[tm1], sl1c[tm1]);
    }
}

// ---------------- K1: persistent Gumbel-max sampler ----------------
__global__ void __launch_bounds__(1024) k_sample(
    const int* __restrict__ x0, const int* __restrict__ ts,
    const float* __restrict__ uni, int B)
{
    const int lane = threadIdx.x & 31;
    Lane L = laneLayout(lane);
    const bool valid = (L.widthL > 0);
    const int c0 = 2 * L.cp;
    const int gw0 = (blockIdx.x * 1024 + threadIdx.x) >> 5;
    const int nw = (gridDim.x * 1024) >> 5;
    const int ntask = B * GROUPS;

    for (int task = gw0; task < ntask; task += nw) {
        const int row = task >> 3, g = task & 7;
        const int t = __ldg(&ts[row]);
        const float2 ca = __ldg(&g_ca2[t]);
        const float lc = ca.x, l1c = ca.y;
        const int feat = g * 5 + L.la;
        const int x0v = valid ? __ldg(&x0[row * F_TOT + feat]) : 0;
        const int hot = L.sstart + x0v;
        const float qb = l1c - L.lnc;

        float2 u = make_float2(0.f, 0.f);
        if (valid) u = *(const float2*)(uni + (size_t)row * D_TOT + g * GCOLS + c0);

        float un0 = (c0 == hot)     ? -1.f : u.x;
        float un1 = (c0 + 1 == hot) ? -1.f : u.y;
        float uv; int ui;
        if (un0 >= un1) { uv = un0; ui = c0; } else { uv = un1; ui = c0 + 1; }
        if (!valid) { uv = -2.f; ui = 0x7FFFFFFF; }
#pragma unroll
        for (int d = 1; d < 16; d <<= 1) {
            float ov = __shfl_xor_sync(FULLM, uv, d);
            int   oi = __shfl_xor_sync(FULLM, ui, d);
            if (L.widthL > d && (ov > uv || (ov == uv && oi < ui))) { uv = ov; ui = oi; }
        }

        const int hlane = cpToLane(hot >> 1);
        const float uh = __shfl_sync(FULLM, (hot & 1) ? u.y : u.x, hlane);

        int win = ui;
        if (valid) {
            const float v_b = -__logf(uv + 1e-30f);
            const float v_h = -__logf(uh + 1e-30f);
            const float zb_f = qb + (-__logf(v_b + 1e-30f));
            const float zh_f = lae_fast(lc, qb) + (-__logf(v_h + 1e-30f));
            const float d = zh_f - zb_f;
            if (uv > 0.996f || uh > 0.996f || fabsf(d) < 1e-3f) {
                const float gb = -logf(-logf(uv + 1e-30f) + 1e-30f);
                const float gh = -logf(-logf(uh + 1e-30f) + 1e-30f);
                const float zb = qb + gb;
                const float zh = lae_prec(lc, qb) + gh;
                win = (zh > zb) ? hot : ((zh == zb) ? min(hot, ui) : ui);
            } else {
                win = (d > 0.f) ? hot : ui;
            }
        }
        if (valid && lane == L.lbase) g_win[row * F_TOT + feat] = g * GCOLS + win;
    }
}

// ---------------- K2: fused gather + posteriors + KL ----------------
// 512 threads, 2 CTAs/SM (128 regs/thread). smem (bytes):
//   [0, 61504)        sW    half2[496*31]
//   [61504, 81984)    sOff  int[CHUNK*40]  (union: colsum scratch)
//   [81984, 82232)    sCs   float2[31]
#define SMEM_OFF 61504
#define SMEM_CS  81984
#define SMEM_K2  (SMEM_CS + 31 * 8 + 8)

__global__ void __launch_bounds__(512, 2) k_fuse(
    const int* __restrict__ x0, const int* __restrict__ ts,
    const float* __restrict__ W, const float* __restrict__ bias,
    const float* __restrict__ temb, int B)
{
    extern __shared__ char smem[];
    half2*  sW   = (half2*)smem;
    int*    sOff = (int*)(smem + SMEM_OFF);
    float2* sScr = (float2*)(smem + SMEM_OFF);
    float2* sCs  = (float2*)(smem + SMEM_CS);

    const int g = blockIdx.y;
    const int tid = threadIdx.x, lane = tid & 31, wid = tid >> 5;
    const int gbase = g * GCOLS;

    // ---- stage W -> fp16 smem, exact fp32 colsum ----
    float2 acc = make_float2(0.f, 0.f);
    for (int r = wid; r < D_TOT; r += 16) {
        if (lane < 31) {
            float2 v = *(const float2*)(W + (size_t)r * D_TOT + gbase + 2 * lane);
            acc.x += v.x; acc.y += v.y;
            sW[r * 31 + lane] = __floats2half2_rn(v.x, v.y);
        }
    }
    if (lane < 31) sScr[wid * 31 + lane] = acc;
    __syncthreads();
    if (tid < 31) {
        float2 s = make_float2(0.f, 0.f);
#pragma unroll
        for (int w2 = 0; w2 < 16; w2++) { float2 a = sScr[w2 * 31 + tid]; s.x += a.x; s.y += a.y; }
        sCs[tid] = s;
    }
    __syncthreads();

    Lane L = laneLayout(lane);
    const bool valid = (L.widthL > 0);
    const float2 cs2 = sCs[L.cp];

    const int per = (B + gridDim.x - 1) / gridDim.x;
    const int r0 = blockIdx.x * per;
    const int r1 = min(r0 + per, B);

    const int C0 = gbase + 2 * L.cp;
    const int feat = g * 5 + L.la;
    const float LOGEPS = -69.07755279f;
    const float2 b2 = *(const float2*)(bias + C0);
    const float NEG = -FLT_MAX;

    // kl_prior per-lane constants (t = T-1)
    const float2 caT = __ldg(&g_ca2[T_STEPS - 1]);
    const float qbT = caT.y - L.lnc;
    const float lqh = lae_fast(caT.x, qbT);
    const float prh = __expf(lqh) * (lqh + L.lnc);
    const float prc = __expf(qbT) * (qbT + L.lnc);

    const int offC0 = C0 * 124, offC1 = offC0 + 124;
    const char* sWb = smem;
    const int cpb = L.cp * 4;

    float lacc = 0.f;                  // per-lane loss accumulator (deferred reduction)

    for (int cr = r0; cr < r1; cr += CHUNK) {
        __syncthreads();
        const int nrows = min(CHUNK, r1 - cr);
        for (int i = tid; i < nrows * F_TOT; i += 512)
            sOff[i] = __ldg(&g_win[cr * F_TOT + i]) * 124;
        __syncthreads();

        for (int rl = wid; rl < nrows; rl += 16) {
            const int row = cr + rl;
            const int t = __ldg(&ts[row]);
            const float4 tb = __ldg(&g_tab4[t]);
            const bool t0 = (t == 0);
            const int x0v = __ldg(&x0[row * F_TOT + feat]);
            const int hot = L.sstart + x0v;
            const bool h0 = (2 * L.cp == hot), h1 = (2 * L.cp + 1 == hot);
            const int myoff = sOff[rl * F_TOT + feat];
            const bool w0 = (myoff == offC0), w1 = (myoff == offC1);

            // ---- gather: 40 fp16 winner rows ----
            const int4* op = (const int4*)(sOff + rl * F_TOT);
            int4 o0 = op[0], o1 = op[1], o2 = op[2], o3 = op[3], o4 = op[4];
            int4 o5 = op[5], o6 = op[6], o7 = op[7], o8 = op[8], o9 = op[9];
            float gx = 0.f, gy = 0.f;
#pragma unroll
            for (int q = 0; q < 10; q++) {
                int4 o = (q==0)?o0:(q==1)?o1:(q==2)?o2:(q==3)?o3:(q==4)?o4:
                         (q==5)?o5:(q==6)?o6:(q==7)?o7:(q==8)?o8:o9;
                half2 a = *(const half2*)(sWb + o.x + cpb);
                half2 b = *(const half2*)(sWb + o.y + cpb);
                half2 c = *(const half2*)(sWb + o.z + cpb);
                half2 d = *(const half2*)(sWb + o.w + cpb);
                half2 s4 = __hadd2(__hadd2(a, b), __hadd2(c, d));
                float2 w2 = __half22float2(s4);
                gx += w2.x; gy += w2.y;
            }
            const float2 te = *(const float2*)(temb + (size_t)t * D_TOT + C0);
            const float p0 = LOGEPS * (cs2.x - gx) + b2.x + te.x;
            const float p1 = LOGEPS * (cs2.y - gy) + b2.y + te.y;

            // per-segment log-softmax of pred
            float m = valid ? fmaxf(p0, p1) : NEG;
            m = segMax(m, L.widthL);
            float s = valid ? (__expf(p0 - m) + __expf(p1 - m)) : 0.f;
            s = segSum(s, L.widthL);
            const float lse = m + __logf(s);
            const float lh00 = p0 - lse, lh01 = p1 - lse;

            // sparse-select logaddexp
            const float qb1 = tb.y - L.lnc;
            const float qbm = tb.w - L.lnc;
            const float qow = lae_fast(tb.x, qb1);
            const float evh = t0 ? 0.f : lae_fast(tb.z, qbm);
            const float evc = t0 ? LOGEPS : qbm;

            const float qo0 = w0 ? qow : qb1, qo1 = w1 ? qow : qb1;
            const float ev0 = h0 ? evh : evc, ev1 = h1 ? evh : evc;
            const float un0 = ev0 + qo0, un1 = ev1 + qo1;

            const float e20 = t0 ? lh00 : lae_fast(lh00 + tb.z, qbm);
            const float e21 = t0 ? lh01 : lae_fast(lh01 + tb.z, qbm);
            const float v20 = e20 + qo0, v21 = e21 + qo1;

            // maxless posterior normalizations
            const float eu0 = valid ? __expf(un0) : 0.f;
            const float eu1 = valid ? __expf(un1) : 0.f;
            const float ew0 = valid ? __expf(v20) : 0.f;
            const float ew1 = valid ? __expf(v21) : 0.f;
            const float s1 = segSum(eu0 + eu1, L.widthL);
            const float s2 = segSum(ew0 + ew1, L.widthL);
            const float n1 = __logf(s1), n2 = __logf(s2);
            const float dn = n2 - n1;
            const float inv1 = __fdividef(1.f, s1);

            const float klL = (eu0 * (un0 - v20 + dn) + eu1 * (un1 - v21 + dn)) * inv1;
            const float deL = (h0 ? (n2 - v20) : 0.f) + (h1 ? (n2 - v21) : 0.f);
            const float prL = (h0 ? prh : prc) + (h1 ? prh : prc);

            lacc += valid ? ((t0 ? deL : klL) * 1000.f + prL) : 0.f;
        }
    }

    // one deferred reduction per warp
#pragma unroll
    for (int d = 1; d < 32; d <<= 1)
        lacc += __shfl_xor_sync(FULLM, lacc, d);
    if (lane == 0)
        g_part[(g * NTILES + blockIdx.x) * 16 + wid] = lacc;
}

// ---------------- deterministic single-kernel mean ----------------
__global__ void k_red(float* __restrict__ out, int B) {
    __shared__ float s[1024];
    const int tid = threadIdx.x;
    const int n = NTILES * GROUPS * 16;
    float a = 0.f;
    for (int i = tid; i < n; i += 1024) a += g_part[i];
    s[tid] = a;
    __syncthreads();
    for (int off = 512; off > 0; off >>= 1) {
        if (tid < off) s[tid] += s[tid + off];
        __syncthreads();
    }
    if (tid == 0) out[0] = s[0] / (float)B;
}

// ---------------- launch ----------------
extern "C" void kernel_launch(void* const* d_in, const int* in_sizes, int n_in,
                              void* d_out, int out_size) {
    const int*   x0   = (const int*)d_in[0];
    const int*   ts   = (const int*)d_in[1];
    const float* uni  = (const float*)d_in[2];
    const float* W    = (const float*)d_in[3];
    const float* bias = (const float*)d_in[4];
    const float* temb = (const float*)d_in[5];
    float* out = (float*)d_out;
    const int B = in_sizes[1];

    cudaFuncSetAttribute(k_fuse, cudaFuncAttributeMaxDynamicSharedMemorySize, SMEM_K2);

    k_prep<<<1, 1024>>>();
    k_sample<<<296, 1024>>>(x0, ts, uni, B);
    dim3 gridF(NTILES, GROUPS);
    k_fuse<<<gridF, 512, SMEM_K2>>>(x0, ts, W, bias, temb, B);
    k_red<<<1, 1024>>>(out, B);
}

// round 8
// speedup vs baseline: 2.6710x; 1.0824x over previous
#include <cuda_runtime.h>
#include <cuda_fp16.h>
#include <cstdint>
#include <math.h>
#include <float.h>

#define D_TOT   496
#define F_TOT   40
#define T_STEPS 1000
#define B_MAX   32768
#define GROUPS  8
#define GCOLS   62
#define NTILES  36
#define CHUNK   128
#define FULLM   0xFFFFFFFFu

// ---------------- device scratch ----------------
__device__ float  g_log_alpha[T_STEPS];
__device__ float  g_log_1m_alpha[T_STEPS];
__device__ float  g_log_ca[T_STEPS];
__device__ float  g_log_1m_ca[T_STEPS];
// per-(t, class-size) tables [T_STEPS*5]
__device__ float4 g_tabA[T_STEPS * 5];   // (qb1, qb1e, qow, qowe)
__device__ float4 g_tabB[T_STEPS * 5];   // (evh, evhe, evc, evce)
__device__ float2 g_tabC[T_STEPS * 5];   // (cam, qbme)
__device__ float2 g_smp [T_STEPS * 5];   // (qb, qhot) for sampler
__device__ int    g_win[B_MAX * F_TOT];
__device__ float  g_part[NTILES * GROUPS * 16];

// ---------------- helpers ----------------
__device__ __forceinline__ float lae_prec(float a, float b) {
    float m = fmaxf(a, b), n = fminf(a, b);
    return m + log1pf(expf(n - m));
}

// Lane layout: each lane owns 2 adjacent columns (one pair) of ONE feature.
// Feature sizes 2,4,8,16,32 at group-local cols [0,2),[2,6),[6,14),[14,30),[30,62).
struct Lane { int la, widthL, lbase, cp, sstart; float lnc; };
__device__ __forceinline__ Lane laneLayout(int lane) {
    Lane L;
    if (lane < 16)      { L.la=4; L.widthL=16; L.lbase=0;  L.cp=15+lane; L.sstart=30; L.lnc=3.46573590f; }
    else if (lane < 24) { L.la=3; L.widthL=8;  L.lbase=16; L.cp=lane-9;  L.sstart=14; L.lnc=2.77258872f; }
    else if (lane < 28) { L.la=2; L.widthL=4;  L.lbase=24; L.cp=lane-21; L.sstart=6;  L.lnc=2.07944154f; }
    else if (lane < 30) { L.la=1; L.widthL=2;  L.lbase=28; L.cp=lane-27; L.sstart=2;  L.lnc=1.38629436f; }
    else if (lane == 30){ L.la=0; L.widthL=1;  L.lbase=30; L.cp=0;       L.sstart=0;  L.lnc=0.69314718f; }
    else                { L.la=0; L.widthL=0;  L.lbase=31; L.cp=0;       L.sstart=0;  L.lnc=0.69314718f; }
    return L;
}
__device__ __forceinline__ int cpToLane(int cp) {
    return (cp >= 15) ? cp - 15 : (cp >= 7) ? cp + 9 : (cp >= 3) ? cp + 21
         : (cp >= 1) ? cp + 27 : 30;
}
__device__ __forceinline__ float segMax(float v, int widthL) {
#pragma unroll
    for (int d = 1; d < 16; d <<= 1) {
        float o = __shfl_xor_sync(FULLM, v, d);
        if (widthL > d) v = fmaxf(v, o);
    }
    return v;
}
__device__ __forceinline__ float segSum(float v, int widthL) {
#pragma unroll
    for (int d = 1; d < 16; d <<= 1) {
        float o = __shfl_xor_sync(FULLM, v, d);
        if (widthL > d) v += o;
    }
    return v;
}

// ---------------- prologue 1: diffusion tables (fp32 + double-single scan) ----------------
__global__ void __launch_bounds__(1024) k_prep() {
    __shared__ float shi[1024], slo[1024];
    const int tid = threadIdx.x;
    float la = 0.f, l1b = 0.f;
    if (tid < T_STEPS) {
        double beta = 1e-4 + (double)tid * ((0.02 - 1e-4) / 999.0);
        float betaf = (float)beta;
        la  = log1pf(-betaf);
        l1b = logf(betaf);
        g_log_alpha[tid] = la;
        g_log_1m_alpha[tid] = l1b;
    }
    shi[tid] = la; slo[tid] = 0.f;
    __syncthreads();
    for (int off = 1; off < 1024; off <<= 1) {
        float ahi = (tid >= off) ? shi[tid - off] : 0.f;
        float alo = (tid >= off) ? slo[tid - off] : 0.f;
        __syncthreads();
        float x = shi[tid];
        float s = x + ahi;
        float bb = s - x;
        float err = (x - (s - bb)) + (ahi - bb);
        float lo = err + slo[tid] + alo;
        float hi2 = s + lo;
        lo = lo - (hi2 - s);
        shi[tid] = hi2; slo[tid] = lo;
        __syncthreads();
    }
    if (tid < T_STEPS) {
        float cum = shi[tid];
        g_log_ca[tid] = cum;
        g_log_1m_ca[tid] = logf(-expm1f(cum));
    }
}

// ---------------- prologue 2: per-(t,la) exp/log tables ----------------
__global__ void __launch_bounds__(1024) k_prep2() {
    const int i = blockIdx.x * 1024 + threadIdx.x;
    if (i >= T_STEPS * 5) return;
    const int t = i / 5, la = i - 5 * t;
    const float lncs[5] = {0.69314718f, 1.38629436f, 2.07944154f, 2.77258872f, 3.46573590f};
    const float lnc = lncs[la];
    const float LOGEPS = -69.07755279f;

    const float qb1 = g_log_1m_alpha[t] - lnc;
    const float qb1e = expf(qb1);
    const float qow = lae_prec(g_log_alpha[t], qb1);
    const float qowe = expf(qow);

    float cam, qbme, evh, evhe, evc, evce;
    if (t == 0) {
        cam = 1.f; qbme = 0.f;
        evh = 0.f; evhe = 1.f;
        evc = LOGEPS; evce = 1e-30f;
    } else {
        const float lcm = g_log_ca[t - 1];
        const float qbm = g_log_1m_ca[t - 1] - lnc;
        cam = expf(lcm);
        qbme = expf(qbm);
        evh = lae_prec(lcm, qbm);
        evhe = expf(evh);
        evc = qbm; evce = qbme;
    }
    g_tabA[i] = make_float4(qb1, qb1e, qow, qowe);
    g_tabB[i] = make_float4(evh, evhe, evc, evce);
    g_tabC[i] = make_float2(cam, qbme);

    const float qb = g_log_1m_ca[t] - lnc;
    g_smp[i] = make_float2(qb, lae_prec(g_log_ca[t], qb));
}

// ---------------- K1: persistent Gumbel-max sampler ----------------
__global__ void __launch_bounds__(1024) k_sample(
    const int* __restrict__ x0, const int* __restrict__ ts,
    const float* __restrict__ uni, int B)
{
    const int lane = threadIdx.x & 31;
    Lane L = laneLayout(lane);
    const bool valid = (L.widthL > 0);
    const int c0 = 2 * L.cp;
    const int gw0 = (blockIdx.x * 1024 + threadIdx.x) >> 5;
    const int nw = (gridDim.x * 1024) >> 5;
    const int ntask = B * GROUPS;

    for (int task = gw0; task < ntask; task += nw) {
        const int row = task >> 3, g = task & 7;
        const int t = __ldg(&ts[row]);
        const float2 sm = __ldg(&g_smp[t * 5 + L.la]);
        const float qb = sm.x, qhot = sm.y;
        const int feat = g * 5 + L.la;
        const int x0v = valid ? __ldg(&x0[row * F_TOT + feat]) : 0;
        const int hot = L.sstart + x0v;

        float2 u = make_float2(0.f, 0.f);
        if (valid) u = *(const float2*)(uni + (size_t)row * D_TOT + g * GCOLS + c0);

        // non-hot u-argmax (gumbel monotone in u)
        float un0 = (c0 == hot)     ? -1.f : u.x;
        float un1 = (c0 + 1 == hot) ? -1.f : u.y;
        float uv; int ui;
        if (un0 >= un1) { uv = un0; ui = c0; } else { uv = un1; ui = c0 + 1; }
        if (!valid) { uv = -2.f; ui = 0x7FFFFFFF; }
#pragma unroll
        for (int d = 1; d < 16; d <<= 1) {
            float ov = __shfl_xor_sync(FULLM, uv, d);
            int   oi = __shfl_xor_sync(FULLM, ui, d);
            if (L.widthL > d && (ov > uv || (ov == uv && oi < ui))) { uv = ov; ui = oi; }
        }

        const int hlane = cpToLane(hot >> 1);
        const float uh = __shfl_sync(FULLM, (hot & 1) ? u.y : u.x, hlane);

        int win = ui;
        if (valid) {
            const float v_b = -__logf(uv + 1e-30f);
            const float v_h = -__logf(uh + 1e-30f);
            const float zb_f = qb + (-__logf(v_b + 1e-30f));
            const float zh_f = qhot + (-__logf(v_h + 1e-30f));
            const float d = zh_f - zb_f;
            if (uv > 0.996f || uh > 0.996f || fabsf(d) < 1e-3f) {
                const float gb = -logf(-logf(uv + 1e-30f) + 1e-30f);
                const float gh = -logf(-logf(uh + 1e-30f) + 1e-30f);
                const float zb = qb + gb;
                const float zh = qhot + gh;
                win = (zh > zb) ? hot : ((zh == zb) ? min(hot, ui) : ui);
            } else {
                win = (d > 0.f) ? hot : ui;
            }
        }
        if (valid && lane == L.lbase) g_win[row * F_TOT + feat] = g * GCOLS + win;
    }
}

// ---------------- K2: fused gather + posteriors + KL (exp-domain) ----------------
// 512 threads, 2 CTAs/SM. smem (bytes):
//   [0, 61504)        sW    half2[496*31]
//   [61504, 81984)    sOff  int[CHUNK*40]  (union: colsum scratch)
//   [81984, 82232)    sCs   float2[31]
#define SMEM_OFF 61504
#define SMEM_CS  81984
#define SMEM_K2  (SMEM_CS + 31 * 8 + 8)

__global__ void __launch_bounds__(512, 2) k_fuse(
    const int* __restrict__ x0, const int* __restrict__ ts,
    const float* __restrict__ W, const float* __restrict__ bias,
    const float* __restrict__ temb, int B)
{
    extern __shared__ char smem[];
    half2*  sW   = (half2*)smem;
    int*    sOff = (int*)(smem + SMEM_OFF);
    float2* sScr = (float2*)(smem + SMEM_OFF);
    float2* sCs  = (float2*)(smem + SMEM_CS);

    const int g = blockIdx.y;
    const int tid = threadIdx.x, lane = tid & 31, wid = tid >> 5;
    const int gbase = g * GCOLS;

    // ---- stage W -> fp16 smem, exact fp32 colsum ----
    float2 acc = make_float2(0.f, 0.f);
    for (int r = wid; r < D_TOT; r += 16) {
        if (lane < 31) {
            float2 v = *(const float2*)(W + (size_t)r * D_TOT + gbase + 2 * lane);
            acc.x += v.x; acc.y += v.y;
            sW[r * 31 + lane] = __floats2half2_rn(v.x, v.y);
        }
    }
    if (lane < 31) sScr[wid * 31 + lane] = acc;
    __syncthreads();
    if (tid < 31) {
        float2 s = make_float2(0.f, 0.f);
#pragma unroll
        for (int w2 = 0; w2 < 16; w2++) { float2 a = sScr[w2 * 31 + tid]; s.x += a.x; s.y += a.y; }
        sCs[tid] = s;
    }
    __syncthreads();

    Lane L = laneLayout(lane);
    const bool valid = (L.widthL > 0);
    const float2 cs2 = sCs[L.cp];

    const int per = (B + gridDim.x - 1) / gridDim.x;
    const int r0 = blockIdx.x * per;
    const int r1 = min(r0 + per, B);

    const int C0 = gbase + 2 * L.cp;
    const int feat = g * 5 + L.la;
    const float LOGEPS = -69.07755279f;
    const float2 b2 = *(const float2*)(bias + C0);
    const float NEG = -FLT_MAX;

    // kl_prior per-lane constants (t = T-1)
    const float lcT = __ldg(&g_log_ca[T_STEPS - 1]);
    const float l1cT = __ldg(&g_log_1m_ca[T_STEPS - 1]);
    const float qbT = l1cT - L.lnc;
    const float lqh = lae_prec(lcT, qbT);
    const float prh = __expf(lqh) * (lqh + L.lnc);
    const float prc = __expf(qbT) * (qbT + L.lnc);

    const int offC0 = C0 * 124, offC1 = offC0 + 124;
    const char* sWb = smem;
    const int cpb = L.cp * 4;

    float lacc = 0.f;

    for (int cr = r0; cr < r1; cr += CHUNK) {
        __syncthreads();
        const int nrows = min(CHUNK, r1 - cr);
        for (int i = tid; i < nrows * F_TOT; i += 512)
            sOff[i] = __ldg(&g_win[cr * F_TOT + i]) * 124;
        __syncthreads();

        for (int rl = wid; rl < nrows; rl += 16) {
            const int row = cr + rl;
            const int t = __ldg(&ts[row]);
            const int ti = t * 5 + L.la;
            const float4 A  = __ldg(&g_tabA[ti]);  // qb1, qb1e, qow, qowe
            const float4 Bv = __ldg(&g_tabB[ti]);  // evh, evhe, evc, evce
            const float2 Cv = __ldg(&g_tabC[ti]);  // cam, qbme
            const bool t0 = (t == 0);
            const int x0v = __ldg(&x0[row * F_TOT + feat]);
            const int hot = L.sstart + x0v;
            const bool h0 = (2 * L.cp == hot), h1 = (2 * L.cp + 1 == hot);
            const int myoff = sOff[rl * F_TOT + feat];
            const bool w0 = (myoff == offC0), w1 = (myoff == offC1);

            // ---- gather: 40 fp16 winner rows ----
            const int4* op = (const int4*)(sOff + rl * F_TOT);
            int4 o0 = op[0], o1 = op[1], o2 = op[2], o3 = op[3], o4 = op[4];
            int4 o5 = op[5], o6 = op[6], o7 = op[7], o8 = op[8], o9 = op[9];
            float gx = 0.f, gy = 0.f;
#pragma unroll
            for (int q = 0; q < 10; q++) {
                int4 o = (q==0)?o0:(q==1)?o1:(q==2)?o2:(q==3)?o3:(q==4)?o4:
                         (q==5)?o5:(q==6)?o6:(q==7)?o7:(q==8)?o8:o9;
                half2 a = *(const half2*)(sWb + o.x + cpb);
                half2 b = *(const half2*)(sWb + o.y + cpb);
                half2 c = *(const half2*)(sWb + o.z + cpb);
                half2 d = *(const half2*)(sWb + o.w + cpb);
                half2 s4 = __hadd2(__hadd2(a, b), __hadd2(c, d));
                float2 w2 = __half22float2(s4);
                gx += w2.x; gy += w2.y;
            }
            const float2 te = *(const float2*)(temb + (size_t)t * D_TOT + C0);
            const float p0 = LOGEPS * (cs2.x - gx) + b2.x + te.x;
            const float p1 = LOGEPS * (cs2.y - gy) + b2.y + te.y;

            // per-segment softmax (exp-domain)
            float m = valid ? fmaxf(p0, p1) : NEG;
            m = segMax(m, L.widthL);
            const float E0 = valid ? __expf(p0 - m) : 0.f;
            const float E1 = valid ? __expf(p1 - m) : 0.f;
            const float s = segSum(E0 + E1, L.widthL);
            const float invs = __fdividef(1.f, s);
            const float lses = __logf(s);
            const float lh00 = p0 - m - lses, lh01 = p1 - m - lses;

            // exp(e2) via table FMA: exp(e2) = (E/s)*cam + qbme
            const float xe20 = E0 * invs * Cv.x + Cv.y;
            const float xe21 = E1 * invs * Cv.x + Cv.y;
            const float e2l0 = t0 ? lh00 : __logf(xe20);
            const float e2l1 = t0 ? lh01 : __logf(xe21);

            const float qo0e = w0 ? A.w : A.y, qo1e = w1 ? A.w : A.y;
            const float qo0l = w0 ? A.z : A.x, qo1l = w1 ? A.z : A.x;
            const float ev0l = h0 ? Bv.x : Bv.z, ev1l = h1 ? Bv.x : Bv.z;
            const float ev0e = h0 ? Bv.y : Bv.w, ev1e = h1 ? Bv.y : Bv.w;

            const float eu0 = ev0e * qo0e, eu1 = ev1e * qo1e;
            const float ew0 = xe20 * qo0e, ew1 = xe21 * qo1e;
            const float s1 = segSum(eu0 + eu1, L.widthL);
            const float s2 = segSum(ew0 + ew1, L.widthL);
            const float n1 = __logf(s1), n2 = __logf(s2);
            const float dn = n2 - n1;
            const float inv1 = __fdividef(1.f, s1);

            const float klL = (eu0 * (ev0l - e2l0 + dn) + eu1 * (ev1l - e2l1 + dn)) * inv1;
            const float deL = (h0 ? (n2 - e2l0 - qo0l) : 0.f) + (h1 ? (n2 - e2l1 - qo1l) : 0.f);
            const float prL = (h0 ? prh : prc) + (h1 ? prh : prc);

            lacc += valid ? ((t0 ? deL : klL) * 1000.f + prL) : 0.f;
        }
    }

#pragma unroll
    for (int d = 1; d < 32; d <<= 1)
        lacc += __shfl_xor_sync(FULLM, lacc, d);
    if (lane == 0)
        g_part[(g * NTILES + blockIdx.x) * 16 + wid] = lacc;
}

// ---------------- deterministic single-kernel mean ----------------
__global__ void k_red(float* __restrict__ out, int B) {
    __shared__ float s[1024];
    const int tid = threadIdx.x;
    const int n = NTILES * GROUPS * 16;
    float a = 0.f;
    for (int i = tid; i < n; i += 1024) a += g_part[i];
    s[tid] = a;
    __syncthreads();
    for (int off = 512; off > 0; off >>= 1) {
        if (tid < off) s[tid] += s[tid + off];
        __syncthreads();
    }
    if (tid == 0) out[0] = s[0] / (float)B;
}

// ---------------- launch ----------------
extern "C" void kernel_launch(void* const* d_in, const int* in_sizes, int n_in,
                              void* d_out, int out_size) {
    const int*   x0   = (const int*)d_in[0];
    const int*   ts   = (const int*)d_in[1];
    const float* uni  = (const float*)d_in[2];
    const float* W    = (const float*)d_in[3];
    const float* bias = (const float*)d_in[4];
    const float* temb = (const float*)d_in[5];
    float* out = (float*)d_out;
    const int B = in_sizes[1];

    cudaFuncSetAttribute(k_fuse, cudaFuncAttributeMaxDynamicSharedMemorySize, SMEM_K2);

    k_prep<<<1, 1024>>>();
    k_prep2<<<5, 1024>>>();
    k_sample<<<296, 1024>>>(x0, ts, uni, B);
    dim3 gridF(NTILES, GROUPS);
    k_fuse<<<gridF, 512, SMEM_K2>>>(x0, ts, W, bias, temb, B);
    k_red<<<1, 1024>>>(out, B);
}